// round 3
// baseline (speedup 1.0000x reference)
#include <cuda_runtime.h>

#define N_NODES 50000
#define N_EDGES 800000
#define DIM 256

// ---- scratch (device globals: no allocation allowed in kernel_launch) ----
__device__ float g_h[(size_t)N_NODES * DIM];   // x @ W
__device__ float g_dinv[N_NODES];              // rsqrt(deg+1)
__device__ int   g_deg[N_NODES];
__device__ int   g_rowstart[N_NODES + 1];
__device__ int   g_cursor[N_NODES];
__device__ int   g_csr_src[N_EDGES];

// ------------------------------------------------------------------
// degree histogram
// ------------------------------------------------------------------
__global__ void k_zero_deg() {
    int i = blockIdx.x * blockDim.x + threadIdx.x;
    if (i < N_NODES) g_deg[i] = 0;
}

__global__ void k_count(const int* __restrict__ ei) {
    int e = blockIdx.x * blockDim.x + threadIdx.x;
    if (e < N_EDGES) {
        int dst = ei[N_EDGES + e];
        atomicAdd(&g_deg[dst], 1);
    }
}

// single-block exclusive scan over 50000 degrees; also produces dinv + cursor
__global__ void k_scan() {
    const int T = 1024;
    const int CHUNK = (N_NODES + T - 1) / T;   // 49
    __shared__ int sums[T];
    int t = threadIdx.x;
    int begin = t * CHUNK;
    int end = min(begin + CHUNK, N_NODES);
    int s = 0;
    for (int i = begin; i < end; ++i) s += g_deg[i];
    sums[t] = s;
    __syncthreads();
    // Hillis-Steele inclusive scan of per-thread sums
    for (int off = 1; off < T; off <<= 1) {
        int v = (t >= off) ? sums[t - off] : 0;
        __syncthreads();
        sums[t] += v;
        __syncthreads();
    }
    int off = sums[t] - s;   // exclusive prefix for this thread's chunk
    for (int i = begin; i < end; ++i) {
        int d = g_deg[i];
        g_rowstart[i] = off;
        g_cursor[i]   = off;
        g_dinv[i]     = rsqrtf((float)(d + 1));   // +1: self-loop
        off += d;
    }
    if (t == T - 1) g_rowstart[N_NODES] = sums[T - 1];
}

__global__ void k_fill(const int* __restrict__ ei) {
    int e = blockIdx.x * blockDim.x + threadIdx.x;
    if (e < N_EDGES) {
        int src = ei[e];
        int dst = ei[N_EDGES + e];
        int pos = atomicAdd(&g_cursor[dst], 1);
        g_csr_src[pos] = src;
    }
}

// ------------------------------------------------------------------
// GEMM: g_h[M,256] = x[M,256] @ W[256,256]   (fp32 SIMT, 64x64x16 tiles)
// ------------------------------------------------------------------
__global__ __launch_bounds__(256) void k_gemm(const float* __restrict__ A,
                                              const float* __restrict__ B) {
    const int BM = 64, BN = 64, BK = 16;
    __shared__ float As[BK][BM];       // transposed A tile
    __shared__ float Bs[BK][BN];

    int tid = threadIdx.x;
    int bm = blockIdx.y * BM;
    int bn = blockIdx.x * BN;

    int tx = tid % 16;                 // col group (4 cols each)
    int ty = tid / 16;                 // row group (4 rows each)

    // load mapping
    int a_m  = tid / 4;                // 0..63
    int a_k4 = (tid % 4) * 4;          // 0,4,8,12
    int b_k  = tid / 16;               // 0..15
    int b_n4 = (tid % 16) * 4;

    float acc[4][4];
#pragma unroll
    for (int i = 0; i < 4; ++i)
#pragma unroll
        for (int j = 0; j < 4; ++j) acc[i][j] = 0.f;

#pragma unroll 1
    for (int k0 = 0; k0 < DIM; k0 += BK) {
        int arow = bm + a_m;
        float4 av = make_float4(0.f, 0.f, 0.f, 0.f);
        if (arow < N_NODES)
            av = *(const float4*)(A + (size_t)arow * DIM + k0 + a_k4);
        As[a_k4 + 0][a_m] = av.x;
        As[a_k4 + 1][a_m] = av.y;
        As[a_k4 + 2][a_m] = av.z;
        As[a_k4 + 3][a_m] = av.w;

        float4 bv = *(const float4*)(B + (size_t)(k0 + b_k) * DIM + bn + b_n4);
        *(float4*)(&Bs[b_k][b_n4]) = bv;
        __syncthreads();

#pragma unroll
        for (int kk = 0; kk < BK; ++kk) {
            float4 ra = *(const float4*)(&As[kk][ty * 4]);
            float4 rb = *(const float4*)(&Bs[kk][tx * 4]);
            float a_[4] = {ra.x, ra.y, ra.z, ra.w};
            float b_[4] = {rb.x, rb.y, rb.z, rb.w};
#pragma unroll
            for (int i = 0; i < 4; ++i)
#pragma unroll
                for (int j = 0; j < 4; ++j)
                    acc[i][j] = fmaf(a_[i], b_[j], acc[i][j]);
        }
        __syncthreads();
    }

#pragma unroll
    for (int i = 0; i < 4; ++i) {
        int row = bm + ty * 4 + i;
        if (row < N_NODES) {
            float4 v = make_float4(acc[i][0], acc[i][1], acc[i][2], acc[i][3]);
            *(float4*)(&g_h[(size_t)row * DIM + bn + tx * 4]) = v;
        }
    }
}

// ------------------------------------------------------------------
// gather-side aggregation + epilogue:
// out = relu( dinv[i]*sum_nbr(h[s]*dinv[s]) + dinv[i]^2*h[i] + b ) + x
// blockDim = (64, 4): 64 threads per node (float4 each), 4 nodes per block
// ------------------------------------------------------------------
__global__ __launch_bounds__(256) void k_agg(const float* __restrict__ x,
                                             const float* __restrict__ bias,
                                             float* __restrict__ out) {
    int node = blockIdx.x * blockDim.y + threadIdx.y;
    if (node >= N_NODES) return;
    int t = threadIdx.x;          // 0..63
    int c4 = t * 4;

    float4 acc = make_float4(0.f, 0.f, 0.f, 0.f);
    int start = g_rowstart[node];
    int end   = g_rowstart[node + 1];

    for (int k = start; k < end; ++k) {
        int s = g_csr_src[k];
        float w = g_dinv[s];
        float4 hv = *(const float4*)(&g_h[(size_t)s * DIM + c4]);
        acc.x = fmaf(hv.x, w, acc.x);
        acc.y = fmaf(hv.y, w, acc.y);
        acc.z = fmaf(hv.z, w, acc.z);
        acc.w = fmaf(hv.w, w, acc.w);
    }

    float di = g_dinv[node];
    float sw = di * di;                         // self-loop norm
    size_t base = (size_t)node * DIM + c4;
    float4 hs = *(const float4*)(&g_h[base]);
    float4 xv = *(const float4*)(&x[base]);
    float4 bv = *(const float4*)(&bias[c4]);

    float4 r;
    r.x = fmaxf(fmaf(di, acc.x, fmaf(sw, hs.x, bv.x)), 0.f) + xv.x;
    r.y = fmaxf(fmaf(di, acc.y, fmaf(sw, hs.y, bv.y)), 0.f) + xv.y;
    r.z = fmaxf(fmaf(di, acc.z, fmaf(sw, hs.z, bv.z)), 0.f) + xv.z;
    r.w = fmaxf(fmaf(di, acc.w, fmaf(sw, hs.w, bv.w)), 0.f) + xv.w;
    *(float4*)(&out[base]) = r;
}

// ------------------------------------------------------------------
extern "C" void kernel_launch(void* const* d_in, const int* in_sizes, int n_in,
                              void* d_out, int out_size) {
    const float* x  = (const float*)d_in[0];
    const int*   ei = (const int*)d_in[1];     // JAX default x64-disabled: int32
    const float* W  = (const float*)d_in[2];
    const float* b  = (const float*)d_in[3];
    float* out = (float*)d_out;

    // GEMM (independent of graph structure work)
    k_gemm<<<dim3(DIM / 64, (N_NODES + 63) / 64), 256>>>(x, W);

    // CSR-by-dst build
    k_zero_deg<<<(N_NODES + 255) / 256, 256>>>();
    k_count<<<(N_EDGES + 255) / 256, 256>>>(ei);
    k_scan<<<1, 1024>>>();
    k_fill<<<(N_EDGES + 255) / 256, 256>>>(ei);

    // gather-side aggregate + epilogue
    dim3 ab(64, 4);
    k_agg<<<(N_NODES + 3) / 4, ab>>>(x, b, out);
}

// round 4
// speedup vs baseline: 1.3003x; 1.3003x over previous
#include <cuda_runtime.h>

#define N_NODES 50000
#define N_EDGES 800000
#define DIM 256

#define SCAN_ELEMS 512
#define SCAN_BLOCKS ((N_NODES + SCAN_ELEMS - 1) / SCAN_ELEMS)   // 98

// ---- scratch (device globals: no allocation allowed in kernel_launch) ----
__device__ float g_h[(size_t)N_NODES * DIM];   // x @ W
__device__ float g_dinv[N_NODES];              // rsqrt(deg+1)
__device__ int   g_deg[N_NODES];
__device__ int   g_rowstart[N_NODES + 1];
__device__ int   g_cursor[N_NODES];
__device__ int   g_csr_src[N_EDGES];
__device__ int   g_blocksum[SCAN_BLOCKS];
__device__ int   g_blockoff[SCAN_BLOCKS];

// ------------------------------------------------------------------
// degree histogram
// ------------------------------------------------------------------
__global__ void k_zero_deg() {
    int i = blockIdx.x * blockDim.x + threadIdx.x;
    if (i < N_NODES) g_deg[i] = 0;
}

__global__ void k_count(const int* __restrict__ ei) {
    int e = blockIdx.x * blockDim.x + threadIdx.x;
    if (e < N_EDGES) {
        int dst = ei[N_EDGES + e];
        atomicAdd(&g_deg[dst], 1);
    }
}

// ---- scan stage 1: per-block sums of 512 degrees ----
__global__ __launch_bounds__(256) void k_scan_partial() {
    __shared__ int red[256];
    int base = blockIdx.x * SCAN_ELEMS + threadIdx.x * 2;
    int s = 0;
    if (base < N_NODES)     s += g_deg[base];
    if (base + 1 < N_NODES) s += g_deg[base + 1];
    red[threadIdx.x] = s;
    __syncthreads();
    for (int off = 128; off > 0; off >>= 1) {
        if (threadIdx.x < off) red[threadIdx.x] += red[threadIdx.x + off];
        __syncthreads();
    }
    if (threadIdx.x == 0) g_blocksum[blockIdx.x] = red[0];
}

// ---- scan stage 2: exclusive scan of 98 block sums (1 block of 128) ----
__global__ __launch_bounds__(128) void k_scan_blocks() {
    __shared__ int sh[128];
    int t = threadIdx.x;
    int v = (t < SCAN_BLOCKS) ? g_blocksum[t] : 0;
    sh[t] = v;
    __syncthreads();
    for (int off = 1; off < 128; off <<= 1) {
        int u = (t >= off) ? sh[t - off] : 0;
        __syncthreads();
        sh[t] += u;
        __syncthreads();
    }
    if (t < SCAN_BLOCKS) g_blockoff[t] = sh[t] - v;   // exclusive
    if (t == 127) g_rowstart[N_NODES] = sh[127];      // total edges
}

// ---- scan stage 3: block-local scan + write rowstart/cursor/dinv ----
__global__ __launch_bounds__(256) void k_scan_write() {
    __shared__ int warp_sums[8];
    int t = threadIdx.x;
    int lane = t & 31, warp = t >> 5;
    int base = blockIdx.x * SCAN_ELEMS + t * 2;

    int v0 = (base < N_NODES) ? g_deg[base] : 0;
    int v1 = (base + 1 < N_NODES) ? g_deg[base + 1] : 0;
    int s = v0 + v1;

    // warp inclusive scan of s
    int inc = s;
#pragma unroll
    for (int off = 1; off < 32; off <<= 1) {
        int u = __shfl_up_sync(0xffffffffu, inc, off);
        if (lane >= off) inc += u;
    }
    if (lane == 31) warp_sums[warp] = inc;
    __syncthreads();
    if (warp == 0) {
        int ws = (lane < 8) ? warp_sums[lane] : 0;
#pragma unroll
        for (int off = 1; off < 8; off <<= 1) {
            int u = __shfl_up_sync(0xffffffffu, ws, off);
            if (lane >= off) ws += u;
        }
        if (lane < 8) warp_sums[lane] = ws;
    }
    __syncthreads();
    int ex = inc - s + (warp > 0 ? warp_sums[warp - 1] : 0) + g_blockoff[blockIdx.x];

    if (base < N_NODES) {
        g_rowstart[base] = ex;
        g_cursor[base]   = ex;
        g_dinv[base]     = rsqrtf((float)(v0 + 1));
    }
    if (base + 1 < N_NODES) {
        g_rowstart[base + 1] = ex + v0;
        g_cursor[base + 1]   = ex + v0;
        g_dinv[base + 1]     = rsqrtf((float)(v1 + 1));
    }
}

__global__ void k_fill(const int* __restrict__ ei) {
    int e = blockIdx.x * blockDim.x + threadIdx.x;
    if (e < N_EDGES) {
        int src = ei[e];
        int dst = ei[N_EDGES + e];
        int pos = atomicAdd(&g_cursor[dst], 1);
        g_csr_src[pos] = src;
    }
}

// ------------------------------------------------------------------
// GEMM: g_h[M,256] = x[M,256] @ W[256,256]   (fp32 SIMT, 64x64x16 tiles)
// ------------------------------------------------------------------
__global__ __launch_bounds__(256) void k_gemm(const float* __restrict__ A,
                                              const float* __restrict__ B) {
    const int BM = 64, BN = 64, BK = 16;
    __shared__ float As[BK][BM];       // transposed A tile
    __shared__ float Bs[BK][BN];

    int tid = threadIdx.x;
    int bm = blockIdx.y * BM;
    int bn = blockIdx.x * BN;

    int tx = tid % 16;                 // col group (4 cols each)
    int ty = tid / 16;                 // row group (4 rows each)

    int a_m  = tid / 4;
    int a_k4 = (tid % 4) * 4;
    int b_k  = tid / 16;
    int b_n4 = (tid % 16) * 4;

    float acc[4][4];
#pragma unroll
    for (int i = 0; i < 4; ++i)
#pragma unroll
        for (int j = 0; j < 4; ++j) acc[i][j] = 0.f;

#pragma unroll 1
    for (int k0 = 0; k0 < DIM; k0 += BK) {
        int arow = bm + a_m;
        float4 av = make_float4(0.f, 0.f, 0.f, 0.f);
        if (arow < N_NODES)
            av = *(const float4*)(A + (size_t)arow * DIM + k0 + a_k4);
        As[a_k4 + 0][a_m] = av.x;
        As[a_k4 + 1][a_m] = av.y;
        As[a_k4 + 2][a_m] = av.z;
        As[a_k4 + 3][a_m] = av.w;

        float4 bv = *(const float4*)(B + (size_t)(k0 + b_k) * DIM + bn + b_n4);
        *(float4*)(&Bs[b_k][b_n4]) = bv;
        __syncthreads();

#pragma unroll
        for (int kk = 0; kk < BK; ++kk) {
            float4 ra = *(const float4*)(&As[kk][ty * 4]);
            float4 rb = *(const float4*)(&Bs[kk][tx * 4]);
            float a_[4] = {ra.x, ra.y, ra.z, ra.w};
            float b_[4] = {rb.x, rb.y, rb.z, rb.w};
#pragma unroll
            for (int i = 0; i < 4; ++i)
#pragma unroll
                for (int j = 0; j < 4; ++j)
                    acc[i][j] = fmaf(a_[i], b_[j], acc[i][j]);
        }
        __syncthreads();
    }

#pragma unroll
    for (int i = 0; i < 4; ++i) {
        int row = bm + ty * 4 + i;
        if (row < N_NODES) {
            float4 v = make_float4(acc[i][0], acc[i][1], acc[i][2], acc[i][3]);
            *(float4*)(&g_h[(size_t)row * DIM + bn + tx * 4]) = v;
        }
    }
}

// ------------------------------------------------------------------
// gather-side aggregation + epilogue (4-way unrolled edge loop for MLP)
// out = relu( dinv[i]*sum_nbr(h[s]*dinv[s]) + dinv[i]^2*h[i] + b ) + x
// ------------------------------------------------------------------
__global__ __launch_bounds__(256) void k_agg(const float* __restrict__ x,
                                             const float* __restrict__ bias,
                                             float* __restrict__ out) {
    int node = blockIdx.x * blockDim.y + threadIdx.y;
    if (node >= N_NODES) return;
    int t = threadIdx.x;          // 0..63
    int c4 = t * 4;

    float4 a0 = make_float4(0.f, 0.f, 0.f, 0.f);
    float4 a1 = make_float4(0.f, 0.f, 0.f, 0.f);
    float4 a2 = make_float4(0.f, 0.f, 0.f, 0.f);
    float4 a3 = make_float4(0.f, 0.f, 0.f, 0.f);

    int start = g_rowstart[node];
    int end   = g_rowstart[node + 1];
    int k = start;

    for (; k + 4 <= end; k += 4) {
        int s0 = g_csr_src[k + 0];
        int s1 = g_csr_src[k + 1];
        int s2 = g_csr_src[k + 2];
        int s3 = g_csr_src[k + 3];
        float w0 = g_dinv[s0], w1 = g_dinv[s1], w2 = g_dinv[s2], w3 = g_dinv[s3];
        float4 h0 = *(const float4*)(&g_h[(size_t)s0 * DIM + c4]);
        float4 h1 = *(const float4*)(&g_h[(size_t)s1 * DIM + c4]);
        float4 h2 = *(const float4*)(&g_h[(size_t)s2 * DIM + c4]);
        float4 h3 = *(const float4*)(&g_h[(size_t)s3 * DIM + c4]);
        a0.x = fmaf(h0.x, w0, a0.x); a0.y = fmaf(h0.y, w0, a0.y);
        a0.z = fmaf(h0.z, w0, a0.z); a0.w = fmaf(h0.w, w0, a0.w);
        a1.x = fmaf(h1.x, w1, a1.x); a1.y = fmaf(h1.y, w1, a1.y);
        a1.z = fmaf(h1.z, w1, a1.z); a1.w = fmaf(h1.w, w1, a1.w);
        a2.x = fmaf(h2.x, w2, a2.x); a2.y = fmaf(h2.y, w2, a2.y);
        a2.z = fmaf(h2.z, w2, a2.z); a2.w = fmaf(h2.w, w2, a2.w);
        a3.x = fmaf(h3.x, w3, a3.x); a3.y = fmaf(h3.y, w3, a3.y);
        a3.z = fmaf(h3.z, w3, a3.z); a3.w = fmaf(h3.w, w3, a3.w);
    }
    for (; k < end; ++k) {
        int s = g_csr_src[k];
        float w = g_dinv[s];
        float4 hv = *(const float4*)(&g_h[(size_t)s * DIM + c4]);
        a0.x = fmaf(hv.x, w, a0.x); a0.y = fmaf(hv.y, w, a0.y);
        a0.z = fmaf(hv.z, w, a0.z); a0.w = fmaf(hv.w, w, a0.w);
    }

    float4 acc;
    acc.x = (a0.x + a1.x) + (a2.x + a3.x);
    acc.y = (a0.y + a1.y) + (a2.y + a3.y);
    acc.z = (a0.z + a1.z) + (a2.z + a3.z);
    acc.w = (a0.w + a1.w) + (a2.w + a3.w);

    float di = g_dinv[node];
    float sw = di * di;                         // self-loop norm
    size_t base = (size_t)node * DIM + c4;
    float4 hs = *(const float4*)(&g_h[base]);
    float4 xv = *(const float4*)(&x[base]);
    float4 bv = *(const float4*)(&bias[c4]);

    float4 r;
    r.x = fmaxf(fmaf(di, acc.x, fmaf(sw, hs.x, bv.x)), 0.f) + xv.x;
    r.y = fmaxf(fmaf(di, acc.y, fmaf(sw, hs.y, bv.y)), 0.f) + xv.y;
    r.z = fmaxf(fmaf(di, acc.z, fmaf(sw, hs.z, bv.z)), 0.f) + xv.z;
    r.w = fmaxf(fmaf(di, acc.w, fmaf(sw, hs.w, bv.w)), 0.f) + xv.w;
    *(float4*)(&out[base]) = r;
}

// ------------------------------------------------------------------
extern "C" void kernel_launch(void* const* d_in, const int* in_sizes, int n_in,
                              void* d_out, int out_size) {
    const float* x  = (const float*)d_in[0];
    const int*   ei = (const int*)d_in[1];     // JAX default x64-disabled: int32
    const float* W  = (const float*)d_in[2];
    const float* b  = (const float*)d_in[3];
    float* out = (float*)d_out;

    // GEMM (independent of graph structure work)
    k_gemm<<<dim3(DIM / 64, (N_NODES + 63) / 64), 256>>>(x, W);

    // CSR-by-dst build
    k_zero_deg<<<(N_NODES + 255) / 256, 256>>>();
    k_count<<<(N_EDGES + 255) / 256, 256>>>(ei);
    k_scan_partial<<<SCAN_BLOCKS, 256>>>();
    k_scan_blocks<<<1, 128>>>();
    k_scan_write<<<SCAN_BLOCKS, 256>>>();
    k_fill<<<(N_EDGES + 255) / 256, 256>>>(ei);

    // gather-side aggregate + epilogue
    dim3 ab(64, 4);
    k_agg<<<(N_NODES + 3) / 4, ab>>>(x, b, out);
}

// round 5
// speedup vs baseline: 1.5603x; 1.2000x over previous
#include <cuda_runtime.h>
#include <cuda_bf16.h>
#include <mma.h>

using namespace nvcuda;

#define N_NODES 50000
#define N_PAD   50048            // 391 * 128
#define N_EDGES 800000
#define DIM 256

#define SCAN_ELEMS 512
#define SCAN_BLOCKS ((N_NODES + SCAN_ELEMS - 1) / SCAN_ELEMS)   // 98

// ---- scratch (device globals: no allocation allowed in kernel_launch) ----
__device__ float          g_h[(size_t)N_PAD * DIM];    // x @ W  (rows >= N_NODES: garbage, never read)
__device__ __nv_bfloat16  g_xh[(size_t)N_PAD * DIM];   // bf16 hi of x
__device__ __nv_bfloat16  g_xl[(size_t)N_PAD * DIM];   // bf16 residual of x
__device__ __nv_bfloat16  g_baug[768 * DIM];           // [wh; wl; wh]
__device__ float g_dinv[N_NODES];
__device__ int   g_deg[N_NODES];
__device__ int   g_rowstart[N_NODES + 1];
__device__ int   g_cursor[N_NODES];
__device__ int   g_csr_src[N_EDGES];
__device__ int   g_blocksum[SCAN_BLOCKS];
__device__ int   g_blockoff[SCAN_BLOCKS];

// ------------------------------------------------------------------
// split-precision conversion
// ------------------------------------------------------------------
__global__ __launch_bounds__(256) void k_convert_x(const float* __restrict__ x) {
    int idx = blockIdx.x * blockDim.x + threadIdx.x;        // one float4 per thread
    if (idx >= N_PAD * DIM / 4) return;
    int row = idx >> 6;                                     // 64 float4 per row
    float4 v = make_float4(0.f, 0.f, 0.f, 0.f);
    if (row < N_NODES) v = *(const float4*)(x + (size_t)idx * 4);

    __nv_bfloat16 h0 = __float2bfloat16(v.x), h1 = __float2bfloat16(v.y);
    __nv_bfloat16 h2 = __float2bfloat16(v.z), h3 = __float2bfloat16(v.w);
    __nv_bfloat16 l0 = __float2bfloat16(v.x - __bfloat162float(h0));
    __nv_bfloat16 l1 = __float2bfloat16(v.y - __bfloat162float(h1));
    __nv_bfloat16 l2 = __float2bfloat16(v.z - __bfloat162float(h2));
    __nv_bfloat16 l3 = __float2bfloat16(v.w - __bfloat162float(h3));

    __nv_bfloat162* ph = (__nv_bfloat162*)(g_xh + (size_t)idx * 4);
    __nv_bfloat162* pl = (__nv_bfloat162*)(g_xl + (size_t)idx * 4);
    ph[0] = __nv_bfloat162(h0, h1); ph[1] = __nv_bfloat162(h2, h3);
    pl[0] = __nv_bfloat162(l0, l1); pl[1] = __nv_bfloat162(l2, l3);
}

__global__ __launch_bounds__(256) void k_convert_w(const float* __restrict__ W) {
    int idx = blockIdx.x * blockDim.x + threadIdx.x;        // 65536 elems
    if (idx >= DIM * DIM) return;
    float v = W[idx];
    __nv_bfloat16 hi = __float2bfloat16(v);
    __nv_bfloat16 lo = __float2bfloat16(v - __bfloat162float(hi));
    g_baug[idx]                 = hi;   // rows   0..255 : wh
    g_baug[DIM * DIM + idx]     = lo;   // rows 256..511 : wl
    g_baug[2 * DIM * DIM + idx] = hi;   // rows 512..767 : wh
}

// ------------------------------------------------------------------
// degree histogram + CSR build
// ------------------------------------------------------------------
__global__ void k_zero_deg() {
    int i = blockIdx.x * blockDim.x + threadIdx.x;
    if (i < N_NODES) g_deg[i] = 0;
}

__global__ void k_count(const int* __restrict__ ei) {
    int e = blockIdx.x * blockDim.x + threadIdx.x;
    if (e < N_EDGES) atomicAdd(&g_deg[ei[N_EDGES + e]], 1);
}

__global__ __launch_bounds__(256) void k_scan_partial() {
    __shared__ int red[256];
    int base = blockIdx.x * SCAN_ELEMS + threadIdx.x * 2;
    int s = 0;
    if (base < N_NODES)     s += g_deg[base];
    if (base + 1 < N_NODES) s += g_deg[base + 1];
    red[threadIdx.x] = s;
    __syncthreads();
    for (int off = 128; off > 0; off >>= 1) {
        if (threadIdx.x < off) red[threadIdx.x] += red[threadIdx.x + off];
        __syncthreads();
    }
    if (threadIdx.x == 0) g_blocksum[blockIdx.x] = red[0];
}

__global__ __launch_bounds__(128) void k_scan_blocks() {
    __shared__ int sh[128];
    int t = threadIdx.x;
    int v = (t < SCAN_BLOCKS) ? g_blocksum[t] : 0;
    sh[t] = v;
    __syncthreads();
    for (int off = 1; off < 128; off <<= 1) {
        int u = (t >= off) ? sh[t - off] : 0;
        __syncthreads();
        sh[t] += u;
        __syncthreads();
    }
    if (t < SCAN_BLOCKS) g_blockoff[t] = sh[t] - v;
    if (t == 127) g_rowstart[N_NODES] = sh[127];
}

__global__ __launch_bounds__(256) void k_scan_write() {
    __shared__ int warp_sums[8];
    int t = threadIdx.x;
    int lane = t & 31, warp = t >> 5;
    int base = blockIdx.x * SCAN_ELEMS + t * 2;

    int v0 = (base < N_NODES) ? g_deg[base] : 0;
    int v1 = (base + 1 < N_NODES) ? g_deg[base + 1] : 0;
    int s = v0 + v1;

    int inc = s;
#pragma unroll
    for (int off = 1; off < 32; off <<= 1) {
        int u = __shfl_up_sync(0xffffffffu, inc, off);
        if (lane >= off) inc += u;
    }
    if (lane == 31) warp_sums[warp] = inc;
    __syncthreads();
    if (warp == 0) {
        int ws = (lane < 8) ? warp_sums[lane] : 0;
#pragma unroll
        for (int off = 1; off < 8; off <<= 1) {
            int u = __shfl_up_sync(0xffffffffu, ws, off);
            if (lane >= off) ws += u;
        }
        if (lane < 8) warp_sums[lane] = ws;
    }
    __syncthreads();
    int ex = inc - s + (warp > 0 ? warp_sums[warp - 1] : 0) + g_blockoff[blockIdx.x];

    if (base < N_NODES) {
        g_rowstart[base] = ex;
        g_cursor[base]   = ex;
        g_dinv[base]     = rsqrtf((float)(v0 + 1));
    }
    if (base + 1 < N_NODES) {
        g_rowstart[base + 1] = ex + v0;
        g_cursor[base + 1]   = ex + v0;
        g_dinv[base + 1]     = rsqrtf((float)(v1 + 1));
    }
}

__global__ void k_fill(const int* __restrict__ ei) {
    int e = blockIdx.x * blockDim.x + threadIdx.x;
    if (e < N_EDGES) {
        int src = ei[e];
        int dst = ei[N_EDGES + e];
        int pos = atomicAdd(&g_cursor[dst], 1);
        g_csr_src[pos] = src;
    }
}

// ------------------------------------------------------------------
// tensor-core GEMM: g_h = [xh|xh|xl] (K=768) @ g_baug  (bf16 wmma, fp32 acc)
// CTA tile 128x128, 8 warps (4x2) of 32x64, K-step 32
// ------------------------------------------------------------------
__global__ __launch_bounds__(256) void k_gemm_tc() {
    const int LDA = 40;    // 32 + 8 pad (bf16 elems)
    const int LDB = 136;   // 128 + 8 pad
    __shared__ __nv_bfloat16 As[128 * LDA];
    __shared__ __nv_bfloat16 Bs[32 * LDB];

    int bm = blockIdx.y * 128;
    int bn = blockIdx.x * 128;
    int tid = threadIdx.x;
    int wid = tid >> 5;
    int wm = wid & 3;          // 0..3 -> 32-row band
    int wn = wid >> 2;         // 0..1 -> 64-col band

    wmma::fragment<wmma::accumulator, 16, 16, 16, float> cf[2][4];
#pragma unroll
    for (int i = 0; i < 2; ++i)
#pragma unroll
        for (int j = 0; j < 4; ++j) wmma::fill_fragment(cf[i][j], 0.f);

    for (int kk = 0; kk < 24; ++kk) {
        int k0 = kk * 32;
        const __nv_bfloat16* Asrc = (k0 < 512) ? g_xh : g_xl;
        int col0 = k0 & 255;

        // A tile: 128 rows x 32 cols = 512 int4 chunks
#pragma unroll
        for (int c = tid; c < 512; c += 256) {
            int row = c >> 2;
            int wi = (c & 3) * 8;
            int4 v = *(const int4*)(Asrc + (size_t)(bm + row) * DIM + col0 + wi);
            *(int4*)(&As[row * LDA + wi]) = v;
        }
        // B tile: 32 rows x 128 cols = 512 int4 chunks
#pragma unroll
        for (int c = tid; c < 512; c += 256) {
            int row = c >> 4;
            int wi = (c & 15) * 8;
            int4 v = *(const int4*)(g_baug + (size_t)(k0 + row) * DIM + bn + wi);
            *(int4*)(&Bs[row * LDB + wi]) = v;
        }
        __syncthreads();

#pragma unroll
        for (int ks = 0; ks < 32; ks += 16) {
            wmma::fragment<wmma::matrix_a, 16, 16, 16, __nv_bfloat16, wmma::row_major> af[2];
            wmma::fragment<wmma::matrix_b, 16, 16, 16, __nv_bfloat16, wmma::row_major> bf[4];
#pragma unroll
            for (int i = 0; i < 2; ++i)
                wmma::load_matrix_sync(af[i], &As[(wm * 32 + i * 16) * LDA + ks], LDA);
#pragma unroll
            for (int j = 0; j < 4; ++j)
                wmma::load_matrix_sync(bf[j], &Bs[ks * LDB + wn * 64 + j * 16], LDB);
#pragma unroll
            for (int i = 0; i < 2; ++i)
#pragma unroll
                for (int j = 0; j < 4; ++j)
                    wmma::mma_sync(cf[i][j], af[i], bf[j], cf[i][j]);
        }
        __syncthreads();
    }

#pragma unroll
    for (int i = 0; i < 2; ++i)
#pragma unroll
        for (int j = 0; j < 4; ++j) {
            int row0 = bm + wm * 32 + i * 16;
            int col0 = bn + wn * 64 + j * 16;
            wmma::store_matrix_sync(&g_h[(size_t)row0 * DIM + col0], cf[i][j],
                                    DIM, wmma::mem_row_major);
        }
}

// ------------------------------------------------------------------
// gather-side aggregation + epilogue (4-way unrolled edge loop for MLP)
// out = relu( dinv[i]*sum_nbr(h[s]*dinv[s]) + dinv[i]^2*h[i] + b ) + x
// ------------------------------------------------------------------
__global__ __launch_bounds__(256) void k_agg(const float* __restrict__ x,
                                             const float* __restrict__ bias,
                                             float* __restrict__ out) {
    int node = blockIdx.x * blockDim.y + threadIdx.y;
    if (node >= N_NODES) return;
    int t = threadIdx.x;          // 0..63
    int c4 = t * 4;

    float4 a0 = make_float4(0.f, 0.f, 0.f, 0.f);
    float4 a1 = make_float4(0.f, 0.f, 0.f, 0.f);
    float4 a2 = make_float4(0.f, 0.f, 0.f, 0.f);
    float4 a3 = make_float4(0.f, 0.f, 0.f, 0.f);

    int start = g_rowstart[node];
    int end   = g_rowstart[node + 1];
    int k = start;

    for (; k + 4 <= end; k += 4) {
        int s0 = g_csr_src[k + 0];
        int s1 = g_csr_src[k + 1];
        int s2 = g_csr_src[k + 2];
        int s3 = g_csr_src[k + 3];
        float w0 = g_dinv[s0], w1 = g_dinv[s1], w2 = g_dinv[s2], w3 = g_dinv[s3];
        float4 h0 = *(const float4*)(&g_h[(size_t)s0 * DIM + c4]);
        float4 h1 = *(const float4*)(&g_h[(size_t)s1 * DIM + c4]);
        float4 h2 = *(const float4*)(&g_h[(size_t)s2 * DIM + c4]);
        float4 h3 = *(const float4*)(&g_h[(size_t)s3 * DIM + c4]);
        a0.x = fmaf(h0.x, w0, a0.x); a0.y = fmaf(h0.y, w0, a0.y);
        a0.z = fmaf(h0.z, w0, a0.z); a0.w = fmaf(h0.w, w0, a0.w);
        a1.x = fmaf(h1.x, w1, a1.x); a1.y = fmaf(h1.y, w1, a1.y);
        a1.z = fmaf(h1.z, w1, a1.z); a1.w = fmaf(h1.w, w1, a1.w);
        a2.x = fmaf(h2.x, w2, a2.x); a2.y = fmaf(h2.y, w2, a2.y);
        a2.z = fmaf(h2.z, w2, a2.z); a2.w = fmaf(h2.w, w2, a2.w);
        a3.x = fmaf(h3.x, w3, a3.x); a3.y = fmaf(h3.y, w3, a3.y);
        a3.z = fmaf(h3.z, w3, a3.z); a3.w = fmaf(h3.w, w3, a3.w);
    }
    for (; k < end; ++k) {
        int s = g_csr_src[k];
        float w = g_dinv[s];
        float4 hv = *(const float4*)(&g_h[(size_t)s * DIM + c4]);
        a0.x = fmaf(hv.x, w, a0.x); a0.y = fmaf(hv.y, w, a0.y);
        a0.z = fmaf(hv.z, w, a0.z); a0.w = fmaf(hv.w, w, a0.w);
    }

    float4 acc;
    acc.x = (a0.x + a1.x) + (a2.x + a3.x);
    acc.y = (a0.y + a1.y) + (a2.y + a3.y);
    acc.z = (a0.z + a1.z) + (a2.z + a3.z);
    acc.w = (a0.w + a1.w) + (a2.w + a3.w);

    float di = g_dinv[node];
    float sw = di * di;                         // self-loop norm
    size_t base = (size_t)node * DIM + c4;
    float4 hs = *(const float4*)(&g_h[base]);
    float4 xv = *(const float4*)(&x[base]);
    float4 bv = *(const float4*)(&bias[c4]);

    float4 r;
    r.x = fmaxf(fmaf(di, acc.x, fmaf(sw, hs.x, bv.x)), 0.f) + xv.x;
    r.y = fmaxf(fmaf(di, acc.y, fmaf(sw, hs.y, bv.y)), 0.f) + xv.y;
    r.z = fmaxf(fmaf(di, acc.z, fmaf(sw, hs.z, bv.z)), 0.f) + xv.z;
    r.w = fmaxf(fmaf(di, acc.w, fmaf(sw, hs.w, bv.w)), 0.f) + xv.w;
    *(float4*)(&out[base]) = r;
}

// ------------------------------------------------------------------
extern "C" void kernel_launch(void* const* d_in, const int* in_sizes, int n_in,
                              void* d_out, int out_size) {
    const float* x  = (const float*)d_in[0];
    const int*   ei = (const int*)d_in[1];     // JAX default x64-disabled: int32
    const float* W  = (const float*)d_in[2];
    const float* b  = (const float*)d_in[3];
    float* out = (float*)d_out;

    // split-precision conversion
    k_convert_x<<<(N_PAD * DIM / 4 + 255) / 256, 256>>>(x);
    k_convert_w<<<(DIM * DIM + 255) / 256, 256>>>(W);

    // tensor-core GEMM
    k_gemm_tc<<<dim3(2, N_PAD / 128), 256>>>();

    // CSR-by-dst build
    k_zero_deg<<<(N_NODES + 255) / 256, 256>>>();
    k_count<<<(N_EDGES + 255) / 256, 256>>>(ei);
    k_scan_partial<<<SCAN_BLOCKS, 256>>>();
    k_scan_blocks<<<1, 128>>>();
    k_scan_write<<<SCAN_BLOCKS, 256>>>();
    k_fill<<<(N_EDGES + 255) / 256, 256>>>(ei);

    // gather-side aggregate + epilogue
    dim3 ab(64, 4);
    k_agg<<<(N_NODES + 3) / 4, ab>>>(x, b, out);
}

// round 6
// speedup vs baseline: 1.5720x; 1.0075x over previous
#include <cuda_runtime.h>
#include <cuda_bf16.h>
#include <mma.h>

using namespace nvcuda;

#define N_NODES 50000
#define N_PAD   50048            // 391 * 128
#define N_EDGES 800000
#define DIM 256

#define SCAN_ELEMS 512
#define SCAN_BLOCKS ((N_NODES + SCAN_ELEMS - 1) / SCAN_ELEMS)   // 98

// ---- scratch (device globals: no allocation allowed in kernel_launch) ----
__device__ float          g_h[(size_t)N_PAD * DIM];    // x @ W (rows >= N_NODES never read)
__device__ __nv_bfloat16  g_baug[768 * DIM];           // [wh; wl; wh]
__device__ float g_dinv[N_NODES];
__device__ int   g_deg[N_NODES];
__device__ int   g_rowstart[N_NODES + 1];
__device__ int   g_cursor[N_NODES];
__device__ int   g_csr_src[N_EDGES];
__device__ int   g_blocksum[SCAN_BLOCKS];
__device__ int   g_blockoff[SCAN_BLOCKS];

// ------------------------------------------------------------------
// W -> bf16 hi/lo augmented B matrix
// ------------------------------------------------------------------
__global__ __launch_bounds__(256) void k_convert_w(const float* __restrict__ W) {
    int idx = blockIdx.x * blockDim.x + threadIdx.x;        // 65536 elems
    if (idx >= DIM * DIM) return;
    float v = W[idx];
    __nv_bfloat16 hi = __float2bfloat16(v);
    __nv_bfloat16 lo = __float2bfloat16(v - __bfloat162float(hi));
    g_baug[idx]                 = hi;   // rows   0..255 : wh
    g_baug[DIM * DIM + idx]     = lo;   // rows 256..511 : wl
    g_baug[2 * DIM * DIM + idx] = hi;   // rows 512..767 : wh
}

// ------------------------------------------------------------------
// degree histogram + CSR build
// ------------------------------------------------------------------
__global__ void k_zero_deg() {
    int i = blockIdx.x * blockDim.x + threadIdx.x;
    if (i < N_NODES) g_deg[i] = 0;
}

__global__ void k_count(const int* __restrict__ ei) {
    int e = blockIdx.x * blockDim.x + threadIdx.x;
    if (e < N_EDGES) atomicAdd(&g_deg[ei[N_EDGES + e]], 1);
}

__global__ __launch_bounds__(256) void k_scan_partial() {
    __shared__ int red[256];
    int base = blockIdx.x * SCAN_ELEMS + threadIdx.x * 2;
    int s = 0;
    if (base < N_NODES)     s += g_deg[base];
    if (base + 1 < N_NODES) s += g_deg[base + 1];
    red[threadIdx.x] = s;
    __syncthreads();
    for (int off = 128; off > 0; off >>= 1) {
        if (threadIdx.x < off) red[threadIdx.x] += red[threadIdx.x + off];
        __syncthreads();
    }
    if (threadIdx.x == 0) g_blocksum[blockIdx.x] = red[0];
}

__global__ __launch_bounds__(128) void k_scan_blocks() {
    __shared__ int sh[128];
    int t = threadIdx.x;
    int v = (t < SCAN_BLOCKS) ? g_blocksum[t] : 0;
    sh[t] = v;
    __syncthreads();
    for (int off = 1; off < 128; off <<= 1) {
        int u = (t >= off) ? sh[t - off] : 0;
        __syncthreads();
        sh[t] += u;
        __syncthreads();
    }
    if (t < SCAN_BLOCKS) g_blockoff[t] = sh[t] - v;
    if (t == 127) g_rowstart[N_NODES] = sh[127];
}

__global__ __launch_bounds__(256) void k_scan_write() {
    __shared__ int warp_sums[8];
    int t = threadIdx.x;
    int lane = t & 31, warp = t >> 5;
    int base = blockIdx.x * SCAN_ELEMS + t * 2;

    int v0 = (base < N_NODES) ? g_deg[base] : 0;
    int v1 = (base + 1 < N_NODES) ? g_deg[base + 1] : 0;
    int s = v0 + v1;

    int inc = s;
#pragma unroll
    for (int off = 1; off < 32; off <<= 1) {
        int u = __shfl_up_sync(0xffffffffu, inc, off);
        if (lane >= off) inc += u;
    }
    if (lane == 31) warp_sums[warp] = inc;
    __syncthreads();
    if (warp == 0) {
        int ws = (lane < 8) ? warp_sums[lane] : 0;
#pragma unroll
        for (int off = 1; off < 8; off <<= 1) {
            int u = __shfl_up_sync(0xffffffffu, ws, off);
            if (lane >= off) ws += u;
        }
        if (lane < 8) warp_sums[lane] = ws;
    }
    __syncthreads();
    int ex = inc - s + (warp > 0 ? warp_sums[warp - 1] : 0) + g_blockoff[blockIdx.x];

    if (base < N_NODES) {
        g_rowstart[base] = ex;
        g_cursor[base]   = ex;
        g_dinv[base]     = rsqrtf((float)(v0 + 1));
    }
    if (base + 1 < N_NODES) {
        g_rowstart[base + 1] = ex + v0;
        g_cursor[base + 1]   = ex + v0;
        g_dinv[base + 1]     = rsqrtf((float)(v1 + 1));
    }
}

__global__ void k_fill(const int* __restrict__ ei) {
    int e = blockIdx.x * blockDim.x + threadIdx.x;
    if (e < N_EDGES) {
        int src = ei[e];
        int dst = ei[N_EDGES + e];
        int pos = atomicAdd(&g_cursor[dst], 1);
        g_csr_src[pos] = src;
    }
}

// ------------------------------------------------------------------
// tensor-core GEMM with fused in-register split:
//   g_h = [xh | xh | xl] (K=768) @ g_baug,  bf16 wmma, fp32 acc
// A tile loader reads fp32 x and produces hi (slices 0,1) / residual (slice 2)
// CTA tile 128x128, 8 warps (4x2) of 32x64, K-step 32
// ------------------------------------------------------------------
__global__ __launch_bounds__(256) void k_gemm_tc(const float* __restrict__ x) {
    const int LDA = 40;    // 32 + 8 pad (bf16 elems)
    const int LDB = 136;   // 128 + 8 pad
    __shared__ __nv_bfloat16 As[128 * LDA];
    __shared__ __nv_bfloat16 Bs[32 * LDB];

    int bm = blockIdx.y * 128;
    int bn = blockIdx.x * 128;
    int tid = threadIdx.x;
    int wid = tid >> 5;
    int wm = wid & 3;          // 0..3 -> 32-row band
    int wn = wid >> 2;         // 0..1 -> 64-col band

    wmma::fragment<wmma::accumulator, 16, 16, 16, float> cf[2][4];
#pragma unroll
    for (int i = 0; i < 2; ++i)
#pragma unroll
        for (int j = 0; j < 4; ++j) wmma::fill_fragment(cf[i][j], 0.f);

    for (int kk = 0; kk < 24; ++kk) {
        int k0 = kk * 32;
        bool take_hi = (k0 < 512);
        int col0 = k0 & 255;

        // A tile: 128 rows x 32 cols fp32 -> bf16 (hi or residual)
        // 1024 float4 chunks over 256 threads
#pragma unroll
        for (int c = tid; c < 1024; c += 256) {
            int row = c >> 3;          // 0..127
            int f   = (c & 7) * 4;     // col offset within 32
            int grow = bm + row;
            float4 v = make_float4(0.f, 0.f, 0.f, 0.f);
            if (grow < N_NODES)
                v = *(const float4*)(x + (size_t)grow * DIM + col0 + f);
            __nv_bfloat16 o0, o1, o2, o3;
            __nv_bfloat16 h0 = __float2bfloat16(v.x);
            __nv_bfloat16 h1 = __float2bfloat16(v.y);
            __nv_bfloat16 h2 = __float2bfloat16(v.z);
            __nv_bfloat16 h3 = __float2bfloat16(v.w);
            if (take_hi) {
                o0 = h0; o1 = h1; o2 = h2; o3 = h3;
            } else {
                o0 = __float2bfloat16(v.x - __bfloat162float(h0));
                o1 = __float2bfloat16(v.y - __bfloat162float(h1));
                o2 = __float2bfloat16(v.z - __bfloat162float(h2));
                o3 = __float2bfloat16(v.w - __bfloat162float(h3));
            }
            __nv_bfloat162* p = (__nv_bfloat162*)(&As[row * LDA + f]);
            p[0] = __nv_bfloat162(o0, o1);
            p[1] = __nv_bfloat162(o2, o3);
        }
        // B tile: 32 rows x 128 cols bf16 = 512 int4 chunks
#pragma unroll
        for (int c = tid; c < 512; c += 256) {
            int row = c >> 4;
            int wi = (c & 15) * 8;
            int4 v = *(const int4*)(g_baug + (size_t)(k0 + row) * DIM + bn + wi);
            *(int4*)(&Bs[row * LDB + wi]) = v;
        }
        __syncthreads();

#pragma unroll
        for (int ks = 0; ks < 32; ks += 16) {
            wmma::fragment<wmma::matrix_a, 16, 16, 16, __nv_bfloat16, wmma::row_major> af[2];
            wmma::fragment<wmma::matrix_b, 16, 16, 16, __nv_bfloat16, wmma::row_major> bf[4];
#pragma unroll
            for (int i = 0; i < 2; ++i)
                wmma::load_matrix_sync(af[i], &As[(wm * 32 + i * 16) * LDA + ks], LDA);
#pragma unroll
            for (int j = 0; j < 4; ++j)
                wmma::load_matrix_sync(bf[j], &Bs[ks * LDB + wn * 64 + j * 16], LDB);
#pragma unroll
            for (int i = 0; i < 2; ++i)
#pragma unroll
                for (int j = 0; j < 4; ++j)
                    wmma::mma_sync(cf[i][j], af[i], bf[j], cf[i][j]);
        }
        __syncthreads();
    }

#pragma unroll
    for (int i = 0; i < 2; ++i)
#pragma unroll
        for (int j = 0; j < 4; ++j) {
            int row0 = bm + wm * 32 + i * 16;
            int col0 = bn + wn * 64 + j * 16;
            wmma::store_matrix_sync(&g_h[(size_t)row0 * DIM + col0], cf[i][j],
                                    DIM, wmma::mem_row_major);
        }
}

// ------------------------------------------------------------------
// gather-side aggregation + epilogue (4-way unrolled edge loop for MLP)
// out = relu( dinv[i]*sum_nbr(h[s]*dinv[s]) + dinv[i]^2*h[i] + b ) + x
// ------------------------------------------------------------------
__global__ __launch_bounds__(256) void k_agg(const float* __restrict__ x,
                                             const float* __restrict__ bias,
                                             float* __restrict__ out) {
    int node = blockIdx.x * blockDim.y + threadIdx.y;
    if (node >= N_NODES) return;
    int t = threadIdx.x;          // 0..63
    int c4 = t * 4;

    float4 a0 = make_float4(0.f, 0.f, 0.f, 0.f);
    float4 a1 = make_float4(0.f, 0.f, 0.f, 0.f);
    float4 a2 = make_float4(0.f, 0.f, 0.f, 0.f);
    float4 a3 = make_float4(0.f, 0.f, 0.f, 0.f);

    int start = g_rowstart[node];
    int end   = g_rowstart[node + 1];
    int k = start;

    for (; k + 4 <= end; k += 4) {
        int s0 = g_csr_src[k + 0];
        int s1 = g_csr_src[k + 1];
        int s2 = g_csr_src[k + 2];
        int s3 = g_csr_src[k + 3];
        float w0 = g_dinv[s0], w1 = g_dinv[s1], w2 = g_dinv[s2], w3 = g_dinv[s3];
        float4 h0 = *(const float4*)(&g_h[(size_t)s0 * DIM + c4]);
        float4 h1 = *(const float4*)(&g_h[(size_t)s1 * DIM + c4]);
        float4 h2 = *(const float4*)(&g_h[(size_t)s2 * DIM + c4]);
        float4 h3 = *(const float4*)(&g_h[(size_t)s3 * DIM + c4]);
        a0.x = fmaf(h0.x, w0, a0.x); a0.y = fmaf(h0.y, w0, a0.y);
        a0.z = fmaf(h0.z, w0, a0.z); a0.w = fmaf(h0.w, w0, a0.w);
        a1.x = fmaf(h1.x, w1, a1.x); a1.y = fmaf(h1.y, w1, a1.y);
        a1.z = fmaf(h1.z, w1, a1.z); a1.w = fmaf(h1.w, w1, a1.w);
        a2.x = fmaf(h2.x, w2, a2.x); a2.y = fmaf(h2.y, w2, a2.y);
        a2.z = fmaf(h2.z, w2, a2.z); a2.w = fmaf(h2.w, w2, a2.w);
        a3.x = fmaf(h3.x, w3, a3.x); a3.y = fmaf(h3.y, w3, a3.y);
        a3.z = fmaf(h3.z, w3, a3.z); a3.w = fmaf(h3.w, w3, a3.w);
    }
    for (; k < end; ++k) {
        int s = g_csr_src[k];
        float w = g_dinv[s];
        float4 hv = *(const float4*)(&g_h[(size_t)s * DIM + c4]);
        a0.x = fmaf(hv.x, w, a0.x); a0.y = fmaf(hv.y, w, a0.y);
        a0.z = fmaf(hv.z, w, a0.z); a0.w = fmaf(hv.w, w, a0.w);
    }

    float4 acc;
    acc.x = (a0.x + a1.x) + (a2.x + a3.x);
    acc.y = (a0.y + a1.y) + (a2.y + a3.y);
    acc.z = (a0.z + a1.z) + (a2.z + a3.z);
    acc.w = (a0.w + a1.w) + (a2.w + a3.w);

    float di = g_dinv[node];
    float sw = di * di;                         // self-loop norm
    size_t base = (size_t)node * DIM + c4;
    float4 hs = *(const float4*)(&g_h[base]);
    float4 xv = *(const float4*)(&x[base]);
    float4 bv = *(const float4*)(&bias[c4]);

    float4 r;
    r.x = fmaxf(fmaf(di, acc.x, fmaf(sw, hs.x, bv.x)), 0.f) + xv.x;
    r.y = fmaxf(fmaf(di, acc.y, fmaf(sw, hs.y, bv.y)), 0.f) + xv.y;
    r.z = fmaxf(fmaf(di, acc.z, fmaf(sw, hs.z, bv.z)), 0.f) + xv.z;
    r.w = fmaxf(fmaf(di, acc.w, fmaf(sw, hs.w, bv.w)), 0.f) + xv.w;
    *(float4*)(&out[base]) = r;
}

// ------------------------------------------------------------------
extern "C" void kernel_launch(void* const* d_in, const int* in_sizes, int n_in,
                              void* d_out, int out_size) {
    const float* x  = (const float*)d_in[0];
    const int*   ei = (const int*)d_in[1];     // JAX default x64-disabled: int32
    const float* W  = (const float*)d_in[2];
    const float* b  = (const float*)d_in[3];
    float* out = (float*)d_out;

    // Fork a side stream so the CSR build (memory/atomic-bound) runs
    // concurrently with the GEMM chain (tensor-bound). Host-side objects only;
    // intentionally not destroyed (capture-participating streams must outlive
    // the capture; a handful of leaked handles per process is harmless).
    cudaStream_t s2;
    cudaEvent_t ev_fork, ev_join;
    cudaStreamCreateWithFlags(&s2, cudaStreamNonBlocking);
    cudaEventCreateWithFlags(&ev_fork, cudaEventDisableTiming);
    cudaEventCreateWithFlags(&ev_join, cudaEventDisableTiming);

    cudaEventRecord(ev_fork, 0);
    cudaStreamWaitEvent(s2, ev_fork, 0);

    // --- branch A (default stream): GEMM chain ---
    k_convert_w<<<(DIM * DIM + 255) / 256, 256>>>(W);
    k_gemm_tc<<<dim3(2, N_PAD / 128), 256>>>(x);

    // --- branch B (s2): CSR-by-dst build ---
    k_zero_deg<<<(N_NODES + 255) / 256, 256, 0, s2>>>();
    k_count<<<(N_EDGES + 255) / 256, 256, 0, s2>>>(ei);
    k_scan_partial<<<SCAN_BLOCKS, 256, 0, s2>>>();
    k_scan_blocks<<<1, 128, 0, s2>>>();
    k_scan_write<<<SCAN_BLOCKS, 256, 0, s2>>>();
    k_fill<<<(N_EDGES + 255) / 256, 256, 0, s2>>>(ei);

    // --- join, then aggregate + epilogue ---
    cudaEventRecord(ev_join, s2);
    cudaStreamWaitEvent(0, ev_join, 0);

    dim3 ab(64, 4);
    k_agg<<<(N_NODES + 3) / 4, ab>>>(x, b, out);
}

// round 7
// speedup vs baseline: 1.8841x; 1.1985x over previous
#include <cuda_runtime.h>
#include <cuda_bf16.h>
#include <mma.h>

using namespace nvcuda;

#define N_NODES 50000
#define N_PAD   50048            // 391 * 128
#define N_EDGES 800000
#define DIM 256

#define SCAN_ELEMS 512
#define SCAN_BLOCKS ((N_NODES + SCAN_ELEMS - 1) / SCAN_ELEMS)   // 98

// ---- scratch (device globals: no allocation allowed in kernel_launch) ----
__device__ float          g_h[(size_t)N_PAD * DIM];    // x @ W (rows >= N_NODES never read)
__device__ __nv_bfloat16  g_wh[DIM * DIM];             // bf16 hi of W
__device__ __nv_bfloat16  g_wl[DIM * DIM];             // bf16 residual of W
__device__ float g_dinv[N_NODES];
__device__ int   g_deg[N_NODES];
__device__ int   g_rowstart[N_NODES + 1];
__device__ int   g_cursor[N_NODES];
__device__ int   g_csr_src[N_EDGES];
__device__ int   g_blocksum[SCAN_BLOCKS];
__device__ int   g_blockoff[SCAN_BLOCKS];

// ------------------------------------------------------------------
// W -> bf16 hi/lo
// ------------------------------------------------------------------
__global__ __launch_bounds__(256) void k_convert_w(const float* __restrict__ W) {
    int idx = blockIdx.x * blockDim.x + threadIdx.x;        // 65536 elems
    if (idx >= DIM * DIM) return;
    float v = W[idx];
    __nv_bfloat16 hi = __float2bfloat16(v);
    __nv_bfloat16 lo = __float2bfloat16(v - __bfloat162float(hi));
    g_wh[idx] = hi;
    g_wl[idx] = lo;
}

// ------------------------------------------------------------------
// degree histogram + CSR build
// ------------------------------------------------------------------
__global__ void k_zero_deg() {
    int i = blockIdx.x * blockDim.x + threadIdx.x;
    if (i < N_NODES) g_deg[i] = 0;
}

__global__ void k_count(const int* __restrict__ ei) {
    int e = blockIdx.x * blockDim.x + threadIdx.x;
    if (e < N_EDGES) atomicAdd(&g_deg[ei[N_EDGES + e]], 1);
}

__global__ __launch_bounds__(256) void k_scan_partial() {
    __shared__ int red[256];
    int base = blockIdx.x * SCAN_ELEMS + threadIdx.x * 2;
    int s = 0;
    if (base < N_NODES)     s += g_deg[base];
    if (base + 1 < N_NODES) s += g_deg[base + 1];
    red[threadIdx.x] = s;
    __syncthreads();
    for (int off = 128; off > 0; off >>= 1) {
        if (threadIdx.x < off) red[threadIdx.x] += red[threadIdx.x + off];
        __syncthreads();
    }
    if (threadIdx.x == 0) g_blocksum[blockIdx.x] = red[0];
}

__global__ __launch_bounds__(128) void k_scan_blocks() {
    __shared__ int sh[128];
    int t = threadIdx.x;
    int v = (t < SCAN_BLOCKS) ? g_blocksum[t] : 0;
    sh[t] = v;
    __syncthreads();
    for (int off = 1; off < 128; off <<= 1) {
        int u = (t >= off) ? sh[t - off] : 0;
        __syncthreads();
        sh[t] += u;
        __syncthreads();
    }
    if (t < SCAN_BLOCKS) g_blockoff[t] = sh[t] - v;
    if (t == 127) g_rowstart[N_NODES] = sh[127];
}

__global__ __launch_bounds__(256) void k_scan_write() {
    __shared__ int warp_sums[8];
    int t = threadIdx.x;
    int lane = t & 31, warp = t >> 5;
    int base = blockIdx.x * SCAN_ELEMS + t * 2;

    int v0 = (base < N_NODES) ? g_deg[base] : 0;
    int v1 = (base + 1 < N_NODES) ? g_deg[base + 1] : 0;
    int s = v0 + v1;

    int inc = s;
#pragma unroll
    for (int off = 1; off < 32; off <<= 1) {
        int u = __shfl_up_sync(0xffffffffu, inc, off);
        if (lane >= off) inc += u;
    }
    if (lane == 31) warp_sums[warp] = inc;
    __syncthreads();
    if (warp == 0) {
        int ws = (lane < 8) ? warp_sums[lane] : 0;
#pragma unroll
        for (int off = 1; off < 8; off <<= 1) {
            int u = __shfl_up_sync(0xffffffffu, ws, off);
            if (lane >= off) ws += u;
        }
        if (lane < 8) warp_sums[lane] = ws;
    }
    __syncthreads();
    int ex = inc - s + (warp > 0 ? warp_sums[warp - 1] : 0) + g_blockoff[blockIdx.x];

    if (base < N_NODES) {
        g_rowstart[base] = ex;
        g_cursor[base]   = ex;
        g_dinv[base]     = rsqrtf((float)(v0 + 1));
    }
    if (base + 1 < N_NODES) {
        g_rowstart[base + 1] = ex + v0;
        g_cursor[base + 1]   = ex + v0;
        g_dinv[base + 1]     = rsqrtf((float)(v1 + 1));
    }
}

__global__ void k_fill(const int* __restrict__ ei) {
    int e = blockIdx.x * blockDim.x + threadIdx.x;
    if (e < N_EDGES) {
        int src = ei[e];
        int dst = ei[N_EDGES + e];
        int pos = atomicAdd(&g_cursor[dst], 1);
        g_csr_src[pos] = src;
    }
}

// ------------------------------------------------------------------
// tensor-core GEMM, split-bf16, x read ONCE:
//   per 32-wide K-chunk: convert A fp32 tile -> Ah, Al (SMEM),
//   load Bh, Bl; acc += Ah@Bh + Ah@Bl + Al@Bh
// CTA tile 128x128, 8 warps (4x2) of 32x64, fp32 accum
// ------------------------------------------------------------------
__global__ __launch_bounds__(256) void k_gemm_tc(const float* __restrict__ x) {
    const int LDA = 40;    // 32 + 8 pad (bf16 elems)
    const int LDB = 136;   // 128 + 8 pad
    __shared__ __nv_bfloat16 Ah[128 * LDA];
    __shared__ __nv_bfloat16 Al[128 * LDA];
    __shared__ __nv_bfloat16 Bh[32 * LDB];
    __shared__ __nv_bfloat16 Bl[32 * LDB];

    int bm = blockIdx.y * 128;
    int bn = blockIdx.x * 128;
    int tid = threadIdx.x;
    int wid = tid >> 5;
    int wm = wid & 3;          // 0..3 -> 32-row band
    int wn = wid >> 2;         // 0..1 -> 64-col band

    wmma::fragment<wmma::accumulator, 16, 16, 16, float> cf[2][4];
#pragma unroll
    for (int i = 0; i < 2; ++i)
#pragma unroll
        for (int j = 0; j < 4; ++j) wmma::fill_fragment(cf[i][j], 0.f);

#pragma unroll 1
    for (int kk = 0; kk < 8; ++kk) {
        int k0 = kk * 32;

        // A tile: 128 rows x 32 cols fp32 -> (hi, lo) bf16; 1024 float4 chunks
#pragma unroll
        for (int c = tid; c < 1024; c += 256) {
            int row = c >> 3;          // 0..127
            int f   = (c & 7) * 4;     // col offset within 32
            int grow = bm + row;
            float4 v = make_float4(0.f, 0.f, 0.f, 0.f);
            if (grow < N_NODES)
                v = *(const float4*)(x + (size_t)grow * DIM + k0 + f);
            __nv_bfloat16 h0 = __float2bfloat16(v.x);
            __nv_bfloat16 h1 = __float2bfloat16(v.y);
            __nv_bfloat16 h2 = __float2bfloat16(v.z);
            __nv_bfloat16 h3 = __float2bfloat16(v.w);
            __nv_bfloat16 l0 = __float2bfloat16(v.x - __bfloat162float(h0));
            __nv_bfloat16 l1 = __float2bfloat16(v.y - __bfloat162float(h1));
            __nv_bfloat16 l2 = __float2bfloat16(v.z - __bfloat162float(h2));
            __nv_bfloat16 l3 = __float2bfloat16(v.w - __bfloat162float(h3));
            __nv_bfloat162* ph = (__nv_bfloat162*)(&Ah[row * LDA + f]);
            __nv_bfloat162* pl = (__nv_bfloat162*)(&Al[row * LDA + f]);
            ph[0] = __nv_bfloat162(h0, h1); ph[1] = __nv_bfloat162(h2, h3);
            pl[0] = __nv_bfloat162(l0, l1); pl[1] = __nv_bfloat162(l2, l3);
        }
        // B tiles: 32 rows x 128 cols bf16, hi and lo; 512 int4 chunks each
#pragma unroll
        for (int c = tid; c < 512; c += 256) {
            int row = c >> 4;
            int wi = (c & 15) * 8;
            size_t off = (size_t)(k0 + row) * DIM + bn + wi;
            *(int4*)(&Bh[row * LDB + wi]) = *(const int4*)(g_wh + off);
            *(int4*)(&Bl[row * LDB + wi]) = *(const int4*)(g_wl + off);
        }
        __syncthreads();

#pragma unroll
        for (int ks = 0; ks < 32; ks += 16) {
            wmma::fragment<wmma::matrix_a, 16, 16, 16, __nv_bfloat16, wmma::row_major> afh[2], afl[2];
            wmma::fragment<wmma::matrix_b, 16, 16, 16, __nv_bfloat16, wmma::row_major> bfh[4], bfl[4];
#pragma unroll
            for (int i = 0; i < 2; ++i) {
                wmma::load_matrix_sync(afh[i], &Ah[(wm * 32 + i * 16) * LDA + ks], LDA);
                wmma::load_matrix_sync(afl[i], &Al[(wm * 32 + i * 16) * LDA + ks], LDA);
            }
#pragma unroll
            for (int j = 0; j < 4; ++j) {
                wmma::load_matrix_sync(bfh[j], &Bh[ks * LDB + wn * 64 + j * 16], LDB);
                wmma::load_matrix_sync(bfl[j], &Bl[ks * LDB + wn * 64 + j * 16], LDB);
            }
#pragma unroll
            for (int i = 0; i < 2; ++i)
#pragma unroll
                for (int j = 0; j < 4; ++j) {
                    wmma::mma_sync(cf[i][j], afh[i], bfh[j], cf[i][j]);
                    wmma::mma_sync(cf[i][j], afh[i], bfl[j], cf[i][j]);
                    wmma::mma_sync(cf[i][j], afl[i], bfh[j], cf[i][j]);
                }
        }
        __syncthreads();
    }

#pragma unroll
    for (int i = 0; i < 2; ++i)
#pragma unroll
        for (int j = 0; j < 4; ++j) {
            int row0 = bm + wm * 32 + i * 16;
            int col0 = bn + wn * 64 + j * 16;
            wmma::store_matrix_sync(&g_h[(size_t)row0 * DIM + col0], cf[i][j],
                                    DIM, wmma::mem_row_major);
        }
}

// ------------------------------------------------------------------
// gather-side aggregation + epilogue (4-way unrolled edge loop for MLP)
// out = relu( dinv[i]*sum_nbr(h[s]*dinv[s]) + dinv[i]^2*h[i] + b ) + x
// ------------------------------------------------------------------
__global__ __launch_bounds__(256) void k_agg(const float* __restrict__ x,
                                             const float* __restrict__ bias,
                                             float* __restrict__ out) {
    int node = blockIdx.x * blockDim.y + threadIdx.y;
    if (node >= N_NODES) return;
    int t = threadIdx.x;          // 0..63
    int c4 = t * 4;

    float4 a0 = make_float4(0.f, 0.f, 0.f, 0.f);
    float4 a1 = make_float4(0.f, 0.f, 0.f, 0.f);
    float4 a2 = make_float4(0.f, 0.f, 0.f, 0.f);
    float4 a3 = make_float4(0.f, 0.f, 0.f, 0.f);

    int start = g_rowstart[node];
    int end   = g_rowstart[node + 1];
    int k = start;

    for (; k + 4 <= end; k += 4) {
        int s0 = g_csr_src[k + 0];
        int s1 = g_csr_src[k + 1];
        int s2 = g_csr_src[k + 2];
        int s3 = g_csr_src[k + 3];
        float w0 = g_dinv[s0], w1 = g_dinv[s1], w2 = g_dinv[s2], w3 = g_dinv[s3];
        float4 h0 = *(const float4*)(&g_h[(size_t)s0 * DIM + c4]);
        float4 h1 = *(const float4*)(&g_h[(size_t)s1 * DIM + c4]);
        float4 h2 = *(const float4*)(&g_h[(size_t)s2 * DIM + c4]);
        float4 h3 = *(const float4*)(&g_h[(size_t)s3 * DIM + c4]);
        a0.x = fmaf(h0.x, w0, a0.x); a0.y = fmaf(h0.y, w0, a0.y);
        a0.z = fmaf(h0.z, w0, a0.z); a0.w = fmaf(h0.w, w0, a0.w);
        a1.x = fmaf(h1.x, w1, a1.x); a1.y = fmaf(h1.y, w1, a1.y);
        a1.z = fmaf(h1.z, w1, a1.z); a1.w = fmaf(h1.w, w1, a1.w);
        a2.x = fmaf(h2.x, w2, a2.x); a2.y = fmaf(h2.y, w2, a2.y);
        a2.z = fmaf(h2.z, w2, a2.z); a2.w = fmaf(h2.w, w2, a2.w);
        a3.x = fmaf(h3.x, w3, a3.x); a3.y = fmaf(h3.y, w3, a3.y);
        a3.z = fmaf(h3.z, w3, a3.z); a3.w = fmaf(h3.w, w3, a3.w);
    }
    for (; k < end; ++k) {
        int s = g_csr_src[k];
        float w = g_dinv[s];
        float4 hv = *(const float4*)(&g_h[(size_t)s * DIM + c4]);
        a0.x = fmaf(hv.x, w, a0.x); a0.y = fmaf(hv.y, w, a0.y);
        a0.z = fmaf(hv.z, w, a0.z); a0.w = fmaf(hv.w, w, a0.w);
    }

    float4 acc;
    acc.x = (a0.x + a1.x) + (a2.x + a3.x);
    acc.y = (a0.y + a1.y) + (a2.y + a3.y);
    acc.z = (a0.z + a1.z) + (a2.z + a3.z);
    acc.w = (a0.w + a1.w) + (a2.w + a3.w);

    float di = g_dinv[node];
    float sw = di * di;                         // self-loop norm
    size_t base = (size_t)node * DIM + c4;
    float4 hs = *(const float4*)(&g_h[base]);
    float4 xv = *(const float4*)(&x[base]);
    float4 bv = *(const float4*)(&bias[c4]);

    float4 r;
    r.x = fmaxf(fmaf(di, acc.x, fmaf(sw, hs.x, bv.x)), 0.f) + xv.x;
    r.y = fmaxf(fmaf(di, acc.y, fmaf(sw, hs.y, bv.y)), 0.f) + xv.y;
    r.z = fmaxf(fmaf(di, acc.z, fmaf(sw, hs.z, bv.z)), 0.f) + xv.z;
    r.w = fmaxf(fmaf(di, acc.w, fmaf(sw, hs.w, bv.w)), 0.f) + xv.w;
    *(float4*)(&out[base]) = r;
}

// ------------------------------------------------------------------
extern "C" void kernel_launch(void* const* d_in, const int* in_sizes, int n_in,
                              void* d_out, int out_size) {
    const float* x  = (const float*)d_in[0];
    const int*   ei = (const int*)d_in[1];     // JAX default x64-disabled: int32
    const float* W  = (const float*)d_in[2];
    const float* b  = (const float*)d_in[3];
    float* out = (float*)d_out;

    // Fork a side stream so the CSR build runs concurrently with the GEMM.
    cudaStream_t s2;
    cudaEvent_t ev_fork, ev_join;
    cudaStreamCreateWithFlags(&s2, cudaStreamNonBlocking);
    cudaEventCreateWithFlags(&ev_fork, cudaEventDisableTiming);
    cudaEventCreateWithFlags(&ev_join, cudaEventDisableTiming);

    cudaEventRecord(ev_fork, 0);
    cudaStreamWaitEvent(s2, ev_fork, 0);

    // --- branch A (default stream): GEMM chain ---
    k_convert_w<<<(DIM * DIM + 255) / 256, 256>>>(W);
    k_gemm_tc<<<dim3(2, N_PAD / 128), 256>>>(x);

    // --- branch B (s2): CSR-by-dst build ---
    k_zero_deg<<<(N_NODES + 255) / 256, 256, 0, s2>>>();
    k_count<<<(N_EDGES + 255) / 256, 256, 0, s2>>>(ei);
    k_scan_partial<<<SCAN_BLOCKS, 256, 0, s2>>>();
    k_scan_blocks<<<1, 128, 0, s2>>>();
    k_scan_write<<<SCAN_BLOCKS, 256, 0, s2>>>();
    k_fill<<<(N_EDGES + 255) / 256, 256, 0, s2>>>(ei);

    // --- join, then aggregate + epilogue ---
    cudaEventRecord(ev_join, s2);
    cudaStreamWaitEvent(0, ev_join, 0);

    dim3 ab(64, 4);
    k_agg<<<(N_NODES + 3) / 4, ab>>>(x, b, out);
}

// round 8
// speedup vs baseline: 2.1390x; 1.1353x over previous
#include <cuda_runtime.h>
#include <cuda_bf16.h>
#include <cuda_fp16.h>
#include <mma.h>

using namespace nvcuda;

#define N_NODES 50000
#define N_PAD   50048            // 391 * 128
#define N_EDGES 800000
#define DIM 256

#define SCAN_ELEMS 512
#define SCAN_BLOCKS ((N_NODES + SCAN_ELEMS - 1) / SCAN_ELEMS)   // 98

// ---- scratch (device globals: no allocation allowed in kernel_launch) ----
__device__ __half         g_hb[(size_t)N_PAD * DIM];   // x @ W, fp16 (rows >= N_NODES never read)
__device__ __nv_bfloat16  g_wh[DIM * DIM];             // bf16 hi of W
__device__ __nv_bfloat16  g_wl[DIM * DIM];             // bf16 residual of W
__device__ float g_dinv[N_NODES];
__device__ int   g_deg[N_NODES];
__device__ int   g_rowstart[N_NODES + 1];
__device__ int   g_cursor[N_NODES];
__device__ int   g_csr_src[N_EDGES];
__device__ int   g_blocksum[SCAN_BLOCKS];
__device__ int   g_blockoff[SCAN_BLOCKS];

// ------------------------------------------------------------------
// W -> bf16 hi/lo
// ------------------------------------------------------------------
__global__ __launch_bounds__(256) void k_convert_w(const float* __restrict__ W) {
    int idx = blockIdx.x * blockDim.x + threadIdx.x;        // 65536 elems
    if (idx >= DIM * DIM) return;
    float v = W[idx];
    __nv_bfloat16 hi = __float2bfloat16(v);
    __nv_bfloat16 lo = __float2bfloat16(v - __bfloat162float(hi));
    g_wh[idx] = hi;
    g_wl[idx] = lo;
}

// ------------------------------------------------------------------
// degree histogram + CSR build
// ------------------------------------------------------------------
__global__ void k_zero_deg() {
    int i = blockIdx.x * blockDim.x + threadIdx.x;
    if (i < N_NODES) g_deg[i] = 0;
}

__global__ void k_count(const int* __restrict__ ei) {
    int e = blockIdx.x * blockDim.x + threadIdx.x;
    if (e < N_EDGES) atomicAdd(&g_deg[ei[N_EDGES + e]], 1);
}

__global__ __launch_bounds__(256) void k_scan_partial() {
    __shared__ int red[256];
    int base = blockIdx.x * SCAN_ELEMS + threadIdx.x * 2;
    int s = 0;
    if (base < N_NODES)     s += g_deg[base];
    if (base + 1 < N_NODES) s += g_deg[base + 1];
    red[threadIdx.x] = s;
    __syncthreads();
    for (int off = 128; off > 0; off >>= 1) {
        if (threadIdx.x < off) red[threadIdx.x] += red[threadIdx.x + off];
        __syncthreads();
    }
    if (threadIdx.x == 0) g_blocksum[blockIdx.x] = red[0];
}

__global__ __launch_bounds__(128) void k_scan_blocks() {
    __shared__ int sh[128];
    int t = threadIdx.x;
    int v = (t < SCAN_BLOCKS) ? g_blocksum[t] : 0;
    sh[t] = v;
    __syncthreads();
    for (int off = 1; off < 128; off <<= 1) {
        int u = (t >= off) ? sh[t - off] : 0;
        __syncthreads();
        sh[t] += u;
        __syncthreads();
    }
    if (t < SCAN_BLOCKS) g_blockoff[t] = sh[t] - v;
    if (t == 127) g_rowstart[N_NODES] = sh[127];
}

__global__ __launch_bounds__(256) void k_scan_write() {
    __shared__ int warp_sums[8];
    int t = threadIdx.x;
    int lane = t & 31, warp = t >> 5;
    int base = blockIdx.x * SCAN_ELEMS + t * 2;

    int v0 = (base < N_NODES) ? g_deg[base] : 0;
    int v1 = (base + 1 < N_NODES) ? g_deg[base + 1] : 0;
    int s = v0 + v1;

    int inc = s;
#pragma unroll
    for (int off = 1; off < 32; off <<= 1) {
        int u = __shfl_up_sync(0xffffffffu, inc, off);
        if (lane >= off) inc += u;
    }
    if (lane == 31) warp_sums[warp] = inc;
    __syncthreads();
    if (warp == 0) {
        int ws = (lane < 8) ? warp_sums[lane] : 0;
#pragma unroll
        for (int off = 1; off < 8; off <<= 1) {
            int u = __shfl_up_sync(0xffffffffu, ws, off);
            if (lane >= off) ws += u;
        }
        if (lane < 8) warp_sums[lane] = ws;
    }
    __syncthreads();
    int ex = inc - s + (warp > 0 ? warp_sums[warp - 1] : 0) + g_blockoff[blockIdx.x];

    if (base < N_NODES) {
        g_rowstart[base] = ex;
        g_cursor[base]   = ex;
        g_dinv[base]     = rsqrtf((float)(v0 + 1));
    }
    if (base + 1 < N_NODES) {
        g_rowstart[base + 1] = ex + v0;
        g_cursor[base + 1]   = ex + v0;
        g_dinv[base + 1]     = rsqrtf((float)(v1 + 1));
    }
}

__global__ void k_fill(const int* __restrict__ ei) {
    int e = blockIdx.x * blockDim.x + threadIdx.x;
    if (e < N_EDGES) {
        int src = ei[e];
        int dst = ei[N_EDGES + e];
        int pos = atomicAdd(&g_cursor[dst], 1);
        g_csr_src[pos] = src;
    }
}

// ------------------------------------------------------------------
// tensor-core GEMM, split-bf16, x read ONCE, fp16 output:
//   per 32-wide K-chunk: convert A fp32 tile -> Ah, Al (SMEM),
//   load Bh, Bl; acc += Ah@Bh + Ah@Bl + Al@Bh   (fp32 accum)
// epilogue: stage per-warp tiles in smem, round to fp16, store g_hb
// CTA tile 128x128, 8 warps (4x2) of 32x64
// ------------------------------------------------------------------
__global__ __launch_bounds__(256) void k_gemm_tc(const float* __restrict__ x) {
    const int LDA = 40;    // 32 + 8 pad (bf16 elems)
    const int LDB = 136;   // 128 + 8 pad
    __shared__ __nv_bfloat16 Ah[128 * LDA];
    __shared__ __nv_bfloat16 Al[128 * LDA];
    __shared__ __nv_bfloat16 Bh[32 * LDB];
    __shared__ __nv_bfloat16 Bl[32 * LDB];
    __shared__ float stage_s[8 * 256];     // per-warp 16x16 fp32 staging

    int bm = blockIdx.y * 128;
    int bn = blockIdx.x * 128;
    int tid = threadIdx.x;
    int wid = tid >> 5;
    int lane = tid & 31;
    int wm = wid & 3;          // 0..3 -> 32-row band
    int wn = wid >> 2;         // 0..1 -> 64-col band

    wmma::fragment<wmma::accumulator, 16, 16, 16, float> cf[2][4];
#pragma unroll
    for (int i = 0; i < 2; ++i)
#pragma unroll
        for (int j = 0; j < 4; ++j) wmma::fill_fragment(cf[i][j], 0.f);

#pragma unroll 1
    for (int kk = 0; kk < 8; ++kk) {
        int k0 = kk * 32;

        // A tile: 128 rows x 32 cols fp32 -> (hi, lo) bf16; 1024 float4 chunks
#pragma unroll
        for (int c = tid; c < 1024; c += 256) {
            int row = c >> 3;          // 0..127
            int f   = (c & 7) * 4;     // col offset within 32
            int grow = bm + row;
            float4 v = make_float4(0.f, 0.f, 0.f, 0.f);
            if (grow < N_NODES)
                v = *(const float4*)(x + (size_t)grow * DIM + k0 + f);
            __nv_bfloat16 h0 = __float2bfloat16(v.x);
            __nv_bfloat16 h1 = __float2bfloat16(v.y);
            __nv_bfloat16 h2 = __float2bfloat16(v.z);
            __nv_bfloat16 h3 = __float2bfloat16(v.w);
            __nv_bfloat16 l0 = __float2bfloat16(v.x - __bfloat162float(h0));
            __nv_bfloat16 l1 = __float2bfloat16(v.y - __bfloat162float(h1));
            __nv_bfloat16 l2 = __float2bfloat16(v.z - __bfloat162float(h2));
            __nv_bfloat16 l3 = __float2bfloat16(v.w - __bfloat162float(h3));
            __nv_bfloat162* ph = (__nv_bfloat162*)(&Ah[row * LDA + f]);
            __nv_bfloat162* pl = (__nv_bfloat162*)(&Al[row * LDA + f]);
            ph[0] = __nv_bfloat162(h0, h1); ph[1] = __nv_bfloat162(h2, h3);
            pl[0] = __nv_bfloat162(l0, l1); pl[1] = __nv_bfloat162(l2, l3);
        }
        // B tiles: 32 rows x 128 cols bf16, hi and lo; 512 int4 chunks each
#pragma unroll
        for (int c = tid; c < 512; c += 256) {
            int row = c >> 4;
            int wi = (c & 15) * 8;
            size_t off = (size_t)(k0 + row) * DIM + bn + wi;
            *(int4*)(&Bh[row * LDB + wi]) = *(const int4*)(g_wh + off);
            *(int4*)(&Bl[row * LDB + wi]) = *(const int4*)(g_wl + off);
        }
        __syncthreads();

#pragma unroll
        for (int ks = 0; ks < 32; ks += 16) {
            wmma::fragment<wmma::matrix_a, 16, 16, 16, __nv_bfloat16, wmma::row_major> afh[2], afl[2];
            wmma::fragment<wmma::matrix_b, 16, 16, 16, __nv_bfloat16, wmma::row_major> bfh[4], bfl[4];
#pragma unroll
            for (int i = 0; i < 2; ++i) {
                wmma::load_matrix_sync(afh[i], &Ah[(wm * 32 + i * 16) * LDA + ks], LDA);
                wmma::load_matrix_sync(afl[i], &Al[(wm * 32 + i * 16) * LDA + ks], LDA);
            }
#pragma unroll
            for (int j = 0; j < 4; ++j) {
                wmma::load_matrix_sync(bfh[j], &Bh[ks * LDB + wn * 64 + j * 16], LDB);
                wmma::load_matrix_sync(bfl[j], &Bl[ks * LDB + wn * 64 + j * 16], LDB);
            }
#pragma unroll
            for (int i = 0; i < 2; ++i)
#pragma unroll
                for (int j = 0; j < 4; ++j) {
                    wmma::mma_sync(cf[i][j], afh[i], bfh[j], cf[i][j]);
                    wmma::mma_sync(cf[i][j], afh[i], bfl[j], cf[i][j]);
                    wmma::mma_sync(cf[i][j], afl[i], bfh[j], cf[i][j]);
                }
        }
        __syncthreads();
    }

    // epilogue: fp32 tile -> fp16 g_hb, via per-warp smem staging
    float* stg = &stage_s[wid * 256];
    int r  = lane >> 1;            // 0..15
    int cs = (lane & 1) * 8;       // 0 or 8
#pragma unroll
    for (int i = 0; i < 2; ++i)
#pragma unroll
        for (int j = 0; j < 4; ++j) {
            wmma::store_matrix_sync(stg, cf[i][j], 16, wmma::mem_row_major);
            __syncwarp();
            int row = bm + wm * 32 + i * 16 + r;
            int col = bn + wn * 64 + j * 16 + cs;
            const float* sp = &stg[r * 16 + cs];
            __half2 p0 = __floats2half2_rn(sp[0], sp[1]);
            __half2 p1 = __floats2half2_rn(sp[2], sp[3]);
            __half2 p2 = __floats2half2_rn(sp[4], sp[5]);
            __half2 p3 = __floats2half2_rn(sp[6], sp[7]);
            uint4 o;
            o.x = *(unsigned*)&p0; o.y = *(unsigned*)&p1;
            o.z = *(unsigned*)&p2; o.w = *(unsigned*)&p3;
            *(uint4*)(&g_hb[(size_t)row * DIM + col]) = o;
            __syncwarp();
        }
}

// ------------------------------------------------------------------
// gather-side aggregation + epilogue, fp16 h rows:
// out = relu( dinv[i]*sum_nbr(h[s]*dinv[s]) + dinv[i]^2*h[i] + b ) + x
// 1 warp per node, each lane owns 8 columns (one uint4 of fp16)
// ------------------------------------------------------------------
__global__ __launch_bounds__(256) void k_agg(const float* __restrict__ x,
                                             const float* __restrict__ bias,
                                             float* __restrict__ out) {
    int node = blockIdx.x * 8 + threadIdx.y;
    if (node >= N_NODES) return;
    int lane = threadIdx.x;            // 0..31
    int c8 = lane * 8;

    float acc0[8], acc1[8];
#pragma unroll
    for (int c = 0; c < 8; ++c) { acc0[c] = 0.f; acc1[c] = 0.f; }

    int start = g_rowstart[node];
    int end   = g_rowstart[node + 1];
    int k = start;

    for (; k + 2 <= end; k += 2) {
        int s0 = g_csr_src[k + 0];
        int s1 = g_csr_src[k + 1];
        float w0 = g_dinv[s0];
        float w1 = g_dinv[s1];
        uint4 v0 = *(const uint4*)(&g_hb[(size_t)s0 * DIM + c8]);
        uint4 v1 = *(const uint4*)(&g_hb[(size_t)s1 * DIM + c8]);
        float2 f;
        f = __half22float2(*(__half2*)&v0.x); acc0[0] = fmaf(f.x, w0, acc0[0]); acc0[1] = fmaf(f.y, w0, acc0[1]);
        f = __half22float2(*(__half2*)&v0.y); acc0[2] = fmaf(f.x, w0, acc0[2]); acc0[3] = fmaf(f.y, w0, acc0[3]);
        f = __half22float2(*(__half2*)&v0.z); acc0[4] = fmaf(f.x, w0, acc0[4]); acc0[5] = fmaf(f.y, w0, acc0[5]);
        f = __half22float2(*(__half2*)&v0.w); acc0[6] = fmaf(f.x, w0, acc0[6]); acc0[7] = fmaf(f.y, w0, acc0[7]);
        f = __half22float2(*(__half2*)&v1.x); acc1[0] = fmaf(f.x, w1, acc1[0]); acc1[1] = fmaf(f.y, w1, acc1[1]);
        f = __half22float2(*(__half2*)&v1.y); acc1[2] = fmaf(f.x, w1, acc1[2]); acc1[3] = fmaf(f.y, w1, acc1[3]);
        f = __half22float2(*(__half2*)&v1.z); acc1[4] = fmaf(f.x, w1, acc1[4]); acc1[5] = fmaf(f.y, w1, acc1[5]);
        f = __half22float2(*(__half2*)&v1.w); acc1[6] = fmaf(f.x, w1, acc1[6]); acc1[7] = fmaf(f.y, w1, acc1[7]);
    }
    if (k < end) {
        int s0 = g_csr_src[k];
        float w0 = g_dinv[s0];
        uint4 v0 = *(const uint4*)(&g_hb[(size_t)s0 * DIM + c8]);
        float2 f;
        f = __half22float2(*(__half2*)&v0.x); acc0[0] = fmaf(f.x, w0, acc0[0]); acc0[1] = fmaf(f.y, w0, acc0[1]);
        f = __half22float2(*(__half2*)&v0.y); acc0[2] = fmaf(f.x, w0, acc0[2]); acc0[3] = fmaf(f.y, w0, acc0[3]);
        f = __half22float2(*(__half2*)&v0.z); acc0[4] = fmaf(f.x, w0, acc0[4]); acc0[5] = fmaf(f.y, w0, acc0[5]);
        f = __half22float2(*(__half2*)&v0.w); acc0[6] = fmaf(f.x, w0, acc0[6]); acc0[7] = fmaf(f.y, w0, acc0[7]);
    }

    float di = g_dinv[node];
    float sw = di * di;                    // self-loop norm
    size_t base = (size_t)node * DIM + c8;

    uint4 vs = *(const uint4*)(&g_hb[base]);
    float hs[8];
    {
        float2 f;
        f = __half22float2(*(__half2*)&vs.x); hs[0] = f.x; hs[1] = f.y;
        f = __half22float2(*(__half2*)&vs.y); hs[2] = f.x; hs[3] = f.y;
        f = __half22float2(*(__half2*)&vs.z); hs[4] = f.x; hs[5] = f.y;
        f = __half22float2(*(__half2*)&vs.w); hs[6] = f.x; hs[7] = f.y;
    }

    float4 xv0 = *(const float4*)(&x[base]);
    float4 xv1 = *(const float4*)(&x[base + 4]);
    float4 bv0 = *(const float4*)(&bias[c8]);
    float4 bv1 = *(const float4*)(&bias[c8 + 4]);
    float xr[8] = {xv0.x, xv0.y, xv0.z, xv0.w, xv1.x, xv1.y, xv1.z, xv1.w};
    float br[8] = {bv0.x, bv0.y, bv0.z, bv0.w, bv1.x, bv1.y, bv1.z, bv1.w};

    float r[8];
#pragma unroll
    for (int c = 0; c < 8; ++c) {
        float a = acc0[c] + acc1[c];
        r[c] = fmaxf(fmaf(di, a, fmaf(sw, hs[c], br[c])), 0.f) + xr[c];
    }
    *(float4*)(&out[base])     = make_float4(r[0], r[1], r[2], r[3]);
    *(float4*)(&out[base + 4]) = make_float4(r[4], r[5], r[6], r[7]);
}

// ------------------------------------------------------------------
extern "C" void kernel_launch(void* const* d_in, const int* in_sizes, int n_in,
                              void* d_out, int out_size) {
    const float* x  = (const float*)d_in[0];
    const int*   ei = (const int*)d_in[1];     // JAX default x64-disabled: int32
    const float* W  = (const float*)d_in[2];
    const float* b  = (const float*)d_in[3];
    float* out = (float*)d_out;

    // Fork a side stream so the CSR build runs concurrently with the GEMM.
    cudaStream_t s2;
    cudaEvent_t ev_fork, ev_join;
    cudaStreamCreateWithFlags(&s2, cudaStreamNonBlocking);
    cudaEventCreateWithFlags(&ev_fork, cudaEventDisableTiming);
    cudaEventCreateWithFlags(&ev_join, cudaEventDisableTiming);

    cudaEventRecord(ev_fork, 0);
    cudaStreamWaitEvent(s2, ev_fork, 0);

    // --- branch A (default stream): GEMM chain ---
    k_convert_w<<<(DIM * DIM + 255) / 256, 256>>>(W);
    k_gemm_tc<<<dim3(2, N_PAD / 128), 256>>>(x);

    // --- branch B (s2): CSR-by-dst build ---
    k_zero_deg<<<(N_NODES + 255) / 256, 256, 0, s2>>>();
    k_count<<<(N_EDGES + 255) / 256, 256, 0, s2>>>(ei);
    k_scan_partial<<<SCAN_BLOCKS, 256, 0, s2>>>();
    k_scan_blocks<<<1, 128, 0, s2>>>();
    k_scan_write<<<SCAN_BLOCKS, 256, 0, s2>>>();
    k_fill<<<(N_EDGES + 255) / 256, 256, 0, s2>>>(ei);

    // --- join, then aggregate + epilogue ---
    cudaEventRecord(ev_join, s2);
    cudaStreamWaitEvent(0, ev_join, 0);

    dim3 ab(32, 8);
    k_agg<<<(N_NODES + 7) / 8, ab>>>(x, b, out);
}

// round 9
// speedup vs baseline: 3.3172x; 1.5508x over previous
#include <cuda_runtime.h>
#include <cuda_fp16.h>
#include <mma.h>

using namespace nvcuda;

#define N_NODES 50000
#define N_PAD   50048            // 391 * 128
#define N_EDGES 800000
#define DIM 256

#define SCAN_ELEMS 512
#define SCAN_BLOCKS ((N_NODES + SCAN_ELEMS - 1) / SCAN_ELEMS)   // 98

// ---- scratch (device globals: no allocation allowed in kernel_launch) ----
__device__ __half g_hb[(size_t)N_PAD * DIM];   // x @ W, fp16 (rows >= N_NODES never read)
__device__ __half g_wf[DIM * DIM];             // fp16 W
__device__ float g_dinv[N_NODES];
__device__ int   g_deg[N_NODES];
__device__ int   g_rowstart[N_NODES + 1];
__device__ int   g_cursor[N_NODES];
__device__ int   g_csr_src[N_EDGES];
__device__ int   g_blocksum[SCAN_BLOCKS];
__device__ int   g_blockoff[SCAN_BLOCKS];

// ------------------------------------------------------------------
// W -> fp16
// ------------------------------------------------------------------
__global__ __launch_bounds__(256) void k_convert_w(const float* __restrict__ W) {
    int idx = blockIdx.x * blockDim.x + threadIdx.x;        // 16384 float4s
    if (idx >= DIM * DIM / 4) return;
    float4 v = *(const float4*)(W + (size_t)idx * 4);
    __half2 p0 = __floats2half2_rn(v.x, v.y);
    __half2 p1 = __floats2half2_rn(v.z, v.w);
    __half2* p = (__half2*)(g_wf + (size_t)idx * 4);
    p[0] = p0; p[1] = p1;
}

// ------------------------------------------------------------------
// degree histogram + CSR build
// ------------------------------------------------------------------
__global__ void k_zero_deg() {
    int i = blockIdx.x * blockDim.x + threadIdx.x;
    if (i < N_NODES) g_deg[i] = 0;
}

__global__ void k_count(const int* __restrict__ ei) {
    int e = blockIdx.x * blockDim.x + threadIdx.x;
    if (e < N_EDGES) atomicAdd(&g_deg[ei[N_EDGES + e]], 1);
}

__global__ __launch_bounds__(256) void k_scan_partial() {
    __shared__ int red[256];
    int base = blockIdx.x * SCAN_ELEMS + threadIdx.x * 2;
    int s = 0;
    if (base < N_NODES)     s += g_deg[base];
    if (base + 1 < N_NODES) s += g_deg[base + 1];
    red[threadIdx.x] = s;
    __syncthreads();
    for (int off = 128; off > 0; off >>= 1) {
        if (threadIdx.x < off) red[threadIdx.x] += red[threadIdx.x + off];
        __syncthreads();
    }
    if (threadIdx.x == 0) g_blocksum[blockIdx.x] = red[0];
}

__global__ __launch_bounds__(128) void k_scan_blocks() {
    __shared__ int sh[128];
    int t = threadIdx.x;
    int v = (t < SCAN_BLOCKS) ? g_blocksum[t] : 0;
    sh[t] = v;
    __syncthreads();
    for (int off = 1; off < 128; off <<= 1) {
        int u = (t >= off) ? sh[t - off] : 0;
        __syncthreads();
        sh[t] += u;
        __syncthreads();
    }
    if (t < SCAN_BLOCKS) g_blockoff[t] = sh[t] - v;
    if (t == 127) g_rowstart[N_NODES] = sh[127];
}

__global__ __launch_bounds__(256) void k_scan_write() {
    __shared__ int warp_sums[8];
    int t = threadIdx.x;
    int lane = t & 31, warp = t >> 5;
    int base = blockIdx.x * SCAN_ELEMS + t * 2;

    int v0 = (base < N_NODES) ? g_deg[base] : 0;
    int v1 = (base + 1 < N_NODES) ? g_deg[base + 1] : 0;
    int s = v0 + v1;

    int inc = s;
#pragma unroll
    for (int off = 1; off < 32; off <<= 1) {
        int u = __shfl_up_sync(0xffffffffu, inc, off);
        if (lane >= off) inc += u;
    }
    if (lane == 31) warp_sums[warp] = inc;
    __syncthreads();
    if (warp == 0) {
        int ws = (lane < 8) ? warp_sums[lane] : 0;
#pragma unroll
        for (int off = 1; off < 8; off <<= 1) {
            int u = __shfl_up_sync(0xffffffffu, ws, off);
            if (lane >= off) ws += u;
        }
        if (lane < 8) warp_sums[lane] = ws;
    }
    __syncthreads();
    int ex = inc - s + (warp > 0 ? warp_sums[warp - 1] : 0) + g_blockoff[blockIdx.x];

    if (base < N_NODES) {
        g_rowstart[base] = ex;
        g_cursor[base]   = ex;
        g_dinv[base]     = rsqrtf((float)(v0 + 1));
    }
    if (base + 1 < N_NODES) {
        g_rowstart[base + 1] = ex + v0;
        g_cursor[base + 1]   = ex + v0;
        g_dinv[base + 1]     = rsqrtf((float)(v1 + 1));
    }
}

__global__ void k_fill(const int* __restrict__ ei) {
    int e = blockIdx.x * blockDim.x + threadIdx.x;
    if (e < N_EDGES) {
        int src = ei[e];
        int dst = ei[N_EDGES + e];
        int pos = atomicAdd(&g_cursor[dst], 1);
        g_csr_src[pos] = src;
    }
}

// ------------------------------------------------------------------
// tensor-core GEMM, pure fp16 inputs, fp32 accum, fp16 output:
//   g_hb = fp16( fp16(x) @ fp16(W) )
// CTA tile 128x128, 8 warps (4x2) of 32x64, K-step 32
// ------------------------------------------------------------------
__global__ __launch_bounds__(256) void k_gemm_tc(const float* __restrict__ x) {
    const int LDA = 40;    // 32 + 8 pad (half elems)
    const int LDB = 136;   // 128 + 8 pad
    __shared__ __half As[128 * LDA];
    __shared__ __half Bs[32 * LDB];
    __shared__ float stage_s[8 * 256];     // per-warp 16x16 fp32 staging

    int bm = blockIdx.y * 128;
    int bn = blockIdx.x * 128;
    int tid = threadIdx.x;
    int wid = tid >> 5;
    int lane = tid & 31;
    int wm = wid & 3;          // 0..3 -> 32-row band
    int wn = wid >> 2;         // 0..1 -> 64-col band

    wmma::fragment<wmma::accumulator, 16, 16, 16, float> cf[2][4];
#pragma unroll
    for (int i = 0; i < 2; ++i)
#pragma unroll
        for (int j = 0; j < 4; ++j) wmma::fill_fragment(cf[i][j], 0.f);

#pragma unroll 1
    for (int kk = 0; kk < 8; ++kk) {
        int k0 = kk * 32;

        // A tile: 128 rows x 32 cols fp32 -> fp16; 1024 float4 chunks
#pragma unroll
        for (int c = tid; c < 1024; c += 256) {
            int row = c >> 3;          // 0..127
            int f   = (c & 7) * 4;     // col offset within 32
            int grow = bm + row;
            float4 v = make_float4(0.f, 0.f, 0.f, 0.f);
            if (grow < N_NODES)
                v = *(const float4*)(x + (size_t)grow * DIM + k0 + f);
            __half2* p = (__half2*)(&As[row * LDA + f]);
            p[0] = __floats2half2_rn(v.x, v.y);
            p[1] = __floats2half2_rn(v.z, v.w);
        }
        // B tile: 32 rows x 128 cols fp16 = 512 int4 chunks
#pragma unroll
        for (int c = tid; c < 512; c += 256) {
            int row = c >> 4;
            int wi = (c & 15) * 8;
            *(int4*)(&Bs[row * LDB + wi]) =
                *(const int4*)(g_wf + (size_t)(k0 + row) * DIM + bn + wi);
        }
        __syncthreads();

#pragma unroll
        for (int ks = 0; ks < 32; ks += 16) {
            wmma::fragment<wmma::matrix_a, 16, 16, 16, __half, wmma::row_major> af[2];
            wmma::fragment<wmma::matrix_b, 16, 16, 16, __half, wmma::row_major> bf[4];
#pragma unroll
            for (int i = 0; i < 2; ++i)
                wmma::load_matrix_sync(af[i], &As[(wm * 32 + i * 16) * LDA + ks], LDA);
#pragma unroll
            for (int j = 0; j < 4; ++j)
                wmma::load_matrix_sync(bf[j], &Bs[ks * LDB + wn * 64 + j * 16], LDB);
#pragma unroll
            for (int i = 0; i < 2; ++i)
#pragma unroll
                for (int j = 0; j < 4; ++j)
                    wmma::mma_sync(cf[i][j], af[i], bf[j], cf[i][j]);
        }
        __syncthreads();
    }

    // epilogue: fp32 tile -> fp16 g_hb, via per-warp smem staging
    float* stg = &stage_s[wid * 256];
    int r  = lane >> 1;            // 0..15
    int cs = (lane & 1) * 8;       // 0 or 8
#pragma unroll
    for (int i = 0; i < 2; ++i)
#pragma unroll
        for (int j = 0; j < 4; ++j) {
            wmma::store_matrix_sync(stg, cf[i][j], 16, wmma::mem_row_major);
            __syncwarp();
            int row = bm + wm * 32 + i * 16 + r;
            int col = bn + wn * 64 + j * 16 + cs;
            const float* sp = &stg[r * 16 + cs];
            __half2 p0 = __floats2half2_rn(sp[0], sp[1]);
            __half2 p1 = __floats2half2_rn(sp[2], sp[3]);
            __half2 p2 = __floats2half2_rn(sp[4], sp[5]);
            __half2 p3 = __floats2half2_rn(sp[6], sp[7]);
            uint4 o;
            o.x = *(unsigned*)&p0; o.y = *(unsigned*)&p1;
            o.z = *(unsigned*)&p2; o.w = *(unsigned*)&p3;
            *(uint4*)(&g_hb[(size_t)row * DIM + col]) = o;
            __syncwarp();
        }
}

// ------------------------------------------------------------------
// gather-side aggregation + epilogue, fp16 h rows:
// out = relu( dinv[i]*sum_nbr(h[s]*dinv[s]) + dinv[i]^2*h[i] + b ) + x
// 1 warp per node, each lane owns 8 columns (one uint4 of fp16)
// ------------------------------------------------------------------
__global__ __launch_bounds__(256) void k_agg(const float* __restrict__ x,
                                             const float* __restrict__ bias,
                                             float* __restrict__ out) {
    int node = blockIdx.x * 8 + threadIdx.y;
    if (node >= N_NODES) return;
    int lane = threadIdx.x;            // 0..31
    int c8 = lane * 8;

    float acc0[8], acc1[8];
#pragma unroll
    for (int c = 0; c < 8; ++c) { acc0[c] = 0.f; acc1[c] = 0.f; }

    int start = g_rowstart[node];
    int end   = g_rowstart[node + 1];
    int k = start;

    for (; k + 2 <= end; k += 2) {
        int s0 = g_csr_src[k + 0];
        int s1 = g_csr_src[k + 1];
        float w0 = g_dinv[s0];
        float w1 = g_dinv[s1];
        uint4 v0 = *(const uint4*)(&g_hb[(size_t)s0 * DIM + c8]);
        uint4 v1 = *(const uint4*)(&g_hb[(size_t)s1 * DIM + c8]);
        float2 f;
        f = __half22float2(*(__half2*)&v0.x); acc0[0] = fmaf(f.x, w0, acc0[0]); acc0[1] = fmaf(f.y, w0, acc0[1]);
        f = __half22float2(*(__half2*)&v0.y); acc0[2] = fmaf(f.x, w0, acc0[2]); acc0[3] = fmaf(f.y, w0, acc0[3]);
        f = __half22float2(*(__half2*)&v0.z); acc0[4] = fmaf(f.x, w0, acc0[4]); acc0[5] = fmaf(f.y, w0, acc0[5]);
        f = __half22float2(*(__half2*)&v0.w); acc0[6] = fmaf(f.x, w0, acc0[6]); acc0[7] = fmaf(f.y, w0, acc0[7]);
        f = __half22float2(*(__half2*)&v1.x); acc1[0] = fmaf(f.x, w1, acc1[0]); acc1[1] = fmaf(f.y, w1, acc1[1]);
        f = __half22float2(*(__half2*)&v1.y); acc1[2] = fmaf(f.x, w1, acc1[2]); acc1[3] = fmaf(f.y, w1, acc1[3]);
        f = __half22float2(*(__half2*)&v1.z); acc1[4] = fmaf(f.x, w1, acc1[4]); acc1[5] = fmaf(f.y, w1, acc1[5]);
        f = __half22float2(*(__half2*)&v1.w); acc1[6] = fmaf(f.x, w1, acc1[6]); acc1[7] = fmaf(f.y, w1, acc1[7]);
    }
    if (k < end) {
        int s0 = g_csr_src[k];
        float w0 = g_dinv[s0];
        uint4 v0 = *(const uint4*)(&g_hb[(size_t)s0 * DIM + c8]);
        float2 f;
        f = __half22float2(*(__half2*)&v0.x); acc0[0] = fmaf(f.x, w0, acc0[0]); acc0[1] = fmaf(f.y, w0, acc0[1]);
        f = __half22float2(*(__half2*)&v0.y); acc0[2] = fmaf(f.x, w0, acc0[2]); acc0[3] = fmaf(f.y, w0, acc0[3]);
        f = __half22float2(*(__half2*)&v0.z); acc0[4] = fmaf(f.x, w0, acc0[4]); acc0[5] = fmaf(f.y, w0, acc0[5]);
        f = __half22float2(*(__half2*)&v0.w); acc0[6] = fmaf(f.x, w0, acc0[6]); acc0[7] = fmaf(f.y, w0, acc0[7]);
    }

    float di = g_dinv[node];
    float sw = di * di;                    // self-loop norm
    size_t base = (size_t)node * DIM + c8;

    uint4 vs = *(const uint4*)(&g_hb[base]);
    float hs[8];
    {
        float2 f;
        f = __half22float2(*(__half2*)&vs.x); hs[0] = f.x; hs[1] = f.y;
        f = __half22float2(*(__half2*)&vs.y); hs[2] = f.x; hs[3] = f.y;
        f = __half22float2(*(__half2*)&vs.z); hs[4] = f.x; hs[5] = f.y;
        f = __half22float2(*(__half2*)&vs.w); hs[6] = f.x; hs[7] = f.y;
    }

    float4 xv0 = *(const float4*)(&x[base]);
    float4 xv1 = *(const float4*)(&x[base + 4]);
    float4 bv0 = *(const float4*)(&bias[c8]);
    float4 bv1 = *(const float4*)(&bias[c8 + 4]);
    float xr[8] = {xv0.x, xv0.y, xv0.z, xv0.w, xv1.x, xv1.y, xv1.z, xv1.w};
    float br[8] = {bv0.x, bv0.y, bv0.z, bv0.w, bv1.x, bv1.y, bv1.z, bv1.w};

    float r[8];
#pragma unroll
    for (int c = 0; c < 8; ++c) {
        float a = acc0[c] + acc1[c];
        r[c] = fmaxf(fmaf(di, a, fmaf(sw, hs[c], br[c])), 0.f) + xr[c];
    }
    *(float4*)(&out[base])     = make_float4(r[0], r[1], r[2], r[3]);
    *(float4*)(&out[base + 4]) = make_float4(r[4], r[5], r[6], r[7]);
}

// ------------------------------------------------------------------
extern "C" void kernel_launch(void* const* d_in, const int* in_sizes, int n_in,
                              void* d_out, int out_size) {
    const float* x  = (const float*)d_in[0];
    const int*   ei = (const int*)d_in[1];     // JAX default x64-disabled: int32
    const float* W  = (const float*)d_in[2];
    const float* b  = (const float*)d_in[3];
    float* out = (float*)d_out;

    // Fork a side stream so the CSR build runs concurrently with the GEMM.
    cudaStream_t s2;
    cudaEvent_t ev_fork, ev_join;
    cudaStreamCreateWithFlags(&s2, cudaStreamNonBlocking);
    cudaEventCreateWithFlags(&ev_fork, cudaEventDisableTiming);
    cudaEventCreateWithFlags(&ev_join, cudaEventDisableTiming);

    cudaEventRecord(ev_fork, 0);
    cudaStreamWaitEvent(s2, ev_fork, 0);

    // --- branch A (default stream): GEMM chain ---
    k_convert_w<<<(DIM * DIM / 4 + 255) / 256, 256>>>(W);
    k_gemm_tc<<<dim3(2, N_PAD / 128), 256>>>(x);

    // --- branch B (s2): CSR-by-dst build ---
    k_zero_deg<<<(N_NODES + 255) / 256, 256, 0, s2>>>();
    k_count<<<(N_EDGES + 255) / 256, 256, 0, s2>>>(ei);
    k_scan_partial<<<SCAN_BLOCKS, 256, 0, s2>>>();
    k_scan_blocks<<<1, 128, 0, s2>>>();
    k_scan_write<<<SCAN_BLOCKS, 256, 0, s2>>>();
    k_fill<<<(N_EDGES + 255) / 256, 256, 0, s2>>>(ei);

    // --- join, then aggregate + epilogue ---
    cudaEventRecord(ev_join, s2);
    cudaStreamWaitEvent(0, ev_join, 0);

    dim3 ab(32, 8);
    k_agg<<<(N_NODES + 7) / 8, ab>>>(x, b, out);
}